// round 14
// baseline (speedup 1.0000x reference)
#include <cuda_runtime.h>
#include <cuda_bf16.h>
#include <cuda_fp16.h>
#include <math.h>
#include <stdint.h>

// Problem constants
#define NN   10000
#define NE   100000
#define HID  600
#define NGS  50
#define NITR 6
#define NZ   100

#define KP   640        // plane row stride (elements)
#define KC   608        // K compute extent
#define KP1  64
#define NPAD 10112
#define GT   1024
#define DMAX 13.86f
#define STG  16384      // stage = A(8KB) + B(8KB)
#define SMEM_BYTES (4 * STG)

// ---------------------------------------------------------------------------
// Scratch
// ---------------------------------------------------------------------------
__device__ __align__(256) __half g_ea [(size_t)GT * KP1];
__device__ __align__(256) __half g_T1 [(size_t)NITR * GT * KP];
__device__ __align__(256) __half g_h  [(size_t)NPAD * KP];
__device__ __align__(256) __half g_ag [(size_t)NPAD * KP];
__device__ __align__(256) __half g_x2 [(size_t)NPAD * KP];
__device__ __align__(256) __half g_xh [(size_t)NPAD * KP];
__device__ __align__(256) __half g_em [(size_t)128 * KP];
__device__ __align__(256) __half g_w1 [(size_t)NITR * 640 * KP1];
__device__ __align__(256) __half g_wb [(size_t)NITR * 4 * 640 * KP];
__device__ __align__(256) __half g_tab[(size_t)NITR * GT * HID];
__device__ float g_xe  [(size_t)NZ * HID];
__device__ float g_Ct  [GT];
__device__ int   g_ei0 [NE];
__device__ float g_efr [NE];
__device__ int   g_cnt [NN];
__device__ int   g_off [NN + 1];
__device__ int   g_rank[NE];
// CSR-ordered edge data (de-indirected)
__device__ int2  g_eri [NE];     // {row, i0}
__device__ float g_efc [NE];     // frac

// ---------------------------------------------------------------------------
// Helpers
// ---------------------------------------------------------------------------
__device__ __forceinline__ uint32_t smem_u32(const void* p) {
    uint32_t a;
    asm("{ .reg .u64 t; cvta.to.shared.u64 t, %1; cvt.u32.u64 %0, t; }" : "=r"(a) : "l"(p));
    return a;
}
__device__ __forceinline__ void ldsm4(uint32_t (&r)[4], uint32_t addr) {
    asm volatile("ldmatrix.sync.aligned.m8n8.x4.shared.b16 {%0,%1,%2,%3}, [%4];"
                 : "=r"(r[0]), "=r"(r[1]), "=r"(r[2]), "=r"(r[3]) : "r"(addr));
}
__device__ __forceinline__ void mma16816h(float (&d)[4], const uint32_t (&a)[4],
                                          uint32_t b0, uint32_t b1) {
    asm volatile("mma.sync.aligned.m16n8k16.row.col.f32.f16.f16.f32 "
                 "{%0,%1,%2,%3}, {%4,%5,%6,%7}, {%8,%9}, {%0,%1,%2,%3};"
                 : "+f"(d[0]), "+f"(d[1]), "+f"(d[2]), "+f"(d[3])
                 : "r"(a[0]), "r"(a[1]), "r"(a[2]), "r"(a[3]), "r"(b0), "r"(b1));
}
__device__ __forceinline__ void cpa16(uint32_t dst, const void* src) {
    asm volatile("cp.async.cg.shared.global [%0], [%1], 16;" :: "r"(dst), "l"(src));
}
__device__ __forceinline__ float ssp_f(float v) {
    float av = fabsf(v);
    return fmaxf(v, 0.0f) + log1pf(expf(-av)) - 0.69314718055994530942f;
}
__device__ __forceinline__ uint32_t pack_h2(float a, float b) {
    __half2 p = __floats2half2_rn(a, b);
    return *(uint32_t*)&p;
}
__device__ __forceinline__ uint2 pack_h4(const float* v) {
    uint2 u;
    u.x = pack_h2(v[0], v[1]);
    u.y = pack_h2(v[2], v[3]);
    return u;
}
__device__ __forceinline__ float4 h4_to_f4(uint2 u) {
    float2 a = __half22float2(*(__half2*)&u.x);
    float2 b = __half22float2(*(__half2*)&u.y);
    return make_float4(a.x, a.y, b.x, b.y);
}

// ---------------------------------------------------------------------------
// Fused prologue
// ---------------------------------------------------------------------------
#define B_TAB  (GT / 256)
#define B_EDGE ((NE + 255) / 256)
#define B_EMB  ((128 * KP) / 1024)
#define B_INIT ((NN * KP) / 1024)

__global__ void prologue_kernel(const int* __restrict__ z, const float* __restrict__ emb,
                                const float* __restrict__ pos, const int* __restrict__ ei,
                                float* __restrict__ hout) {
    int bx = blockIdx.x;
    if (bx < B_TAB) {
        int g = bx * 256 + threadIdx.x;
        float d = (float)g * (DMAX / (float)(GT - 1));
        g_Ct[g] = 0.5f * (cosf(d * (float)(M_PI / 10.0)) + 1.0f);
        const float step  = 10.0f / 49.0f;
        const float coeff = -0.5f / (step * step);
        __half* eh = g_ea + (size_t)g * KP1;
#pragma unroll 8
        for (int k = 0; k < KP1; k++) {
            float v = 0.0f;
            if (k < NGS) { float t = d - step * (float)k; v = expf(coeff * t * t); }
            eh[k] = __float2half_rn(v);
        }
    } else if (bx < B_TAB + B_EDGE) {
        int e = (bx - B_TAB) * 256 + threadIdx.x;
        if (e >= NE) return;
        int r = ei[e], c = ei[NE + e];
        float dx = pos[3*r+0] - pos[3*c+0];
        float dy = pos[3*r+1] - pos[3*c+1];
        float dz = pos[3*r+2] - pos[3*c+2];
        float d = sqrtf(dx*dx + dy*dy + dz*dz);
        float t = d * ((float)(GT - 1) / DMAX);
        int i0 = (int)t;
        if (i0 > GT - 2) i0 = GT - 2;
        g_ei0[e] = i0;
        g_efr[e] = t - (float)i0;
        g_rank[e] = atomicAdd(&g_cnt[c], 1);
    } else if (bx < B_TAB + B_EDGE + B_EMB) {
        long i = ((long)(bx - B_TAB - B_EDGE) * 256 + threadIdx.x) * 4;
        int r = (int)(i / KP), k = (int)(i - (long)r * KP);
        float v[4] = {0.f, 0.f, 0.f, 0.f};
        if (r < NZ && k < HID) *(float4*)v = *(const float4*)(emb + (size_t)r * HID + k);
        *(uint2*)(g_em + i) = pack_h4(v);
    } else {
        long i = ((long)(bx - B_TAB - B_EDGE - B_EMB) * 256 + threadIdx.x) * 4;
        int n = (int)(i / KP), k = (int)(i - (long)n * KP);
        float v[4] = {0.f, 0.f, 0.f, 0.f};
        if (k < HID) {
            *(float4*)v = *(const float4*)(emb + (size_t)z[n] * HID + k);
            *(float4*)(hout + (size_t)n * HID + k) = *(float4*)v;
        }
        *(uint2*)(g_h + i) = pack_h4(v);
    }
}

// Exclusive scan of g_cnt -> g_off
__global__ __launch_bounds__(1024)
void csr_scan_kernel() {
    __shared__ int part[1024];
    int t = threadIdx.x;
    int base = t * 10;
    int loc[10];
    int s = 0;
#pragma unroll
    for (int i = 0; i < 10; i++) {
        int idx = base + i;
        loc[i] = s;
        s += (idx < NN) ? g_cnt[idx] : 0;
    }
    part[t] = s;
    __syncthreads();
    for (int off = 1; off < 1024; off <<= 1) {
        int v = (t >= off) ? part[t - off] : 0;
        __syncthreads();
        if (t >= off) part[t] += v;
        __syncthreads();
    }
    int pre = (t > 0) ? part[t - 1] : 0;
#pragma unroll
    for (int i = 0; i < 10; i++) {
        int idx = base + i;
        if (idx < NN) g_off[idx] = pre + loc[i];
    }
    if (t == 1023) g_off[NN] = part[1023];
}

// Place edges into CSR order with de-indirected payload {row, i0, frac}
__global__ void csr_place_kernel(const int* __restrict__ ei) {
    int e = blockIdx.x * blockDim.x + threadIdx.x;
    if (e >= NE) return;
    int c = ei[NE + e];
    int j = g_off[c] + g_rank[e];
    g_eri[j] = make_int2(ei[e], g_ei0[e]);
    g_efc[j] = g_efr[e];
}

// Batched 4-wide convert of 24 HID x HID weights
__global__ void cvt_wb_kernel(const float* __restrict__ w2, const float* __restrict__ l1,
                              const float* __restrict__ l2, const float* __restrict__ lw) {
    int zz = blockIdx.z;
    int wix = zz & 3, it = zz >> 2;
    const float* src = ((wix == 0) ? w2 : (wix == 1) ? l1 : (wix == 2) ? l2 : lw)
                       + (size_t)it * HID * HID;
    __half* dh = g_wb + (size_t)zz * 640 * KP;
    long i = ((long)blockIdx.x * blockDim.x + threadIdx.x) * 4;
    if (i >= (long)600 * KP) return;
    int r = (int)(i / KP), k = (int)(i - (long)r * KP);
    float v[4] = {0.f, 0.f, 0.f, 0.f};
    if (k < HID) *(float4*)v = *(const float4*)(src + (size_t)r * HID + k);
    *(uint2*)(dh + i) = pack_h4(v);
}

__global__ void cvt_w1_kernel(const float* __restrict__ w1) {
    int it = blockIdx.z;
    const float* src = w1 + (size_t)it * HID * NGS;
    __half* dh = g_w1 + (size_t)it * 640 * KP1;
    long i = blockIdx.x * (long)blockDim.x + threadIdx.x;
    if (i >= (long)600 * KP1) return;
    int r = (int)(i / KP1), k = (int)(i - (long)r * KP1);
    float v = (k < NGS) ? src[(size_t)r * NGS + k] : 0.0f;
    dh[i] = __float2half_rn(v);
}

// x plane[n] = fp16(xe[z[n]])
__global__ void xgather_kernel(const int* __restrict__ z, const float* __restrict__ xe,
                               __half* __restrict__ xh) {
    long i = ((long)blockIdx.x * blockDim.x + threadIdx.x) * 4;
    if (i >= (long)NN * HID) return;
    int n = (int)(i / HID), k = (int)(i - (long)n * HID);
    float v[4];
    *(float4*)v = *(const float4*)(xe + (size_t)z[n] * HID + k);
    *(uint2*)(xh + (size_t)n * KP + k) = pack_h4(v);
}

// ---------------------------------------------------------------------------
// fp16 HMMA GEMM, 128x128 tile, 3 CTAs/SM (streamed A frags), 4-stage pipeline
// OUTM: 0 fp32 Cf; 1 fp16 plane (zero-pads); 2 fp32 residual + plane; 3 fp16 valid-only
// ---------------------------------------------------------------------------
template <int DO_BIAS, int DO_SSP, int DO_RSCALE, int OUTM>
__global__ __launch_bounds__(256, 3)
void hgemm(const __half* __restrict__ A, const __half* __restrict__ B,
           const float* __restrict__ bias, const float* __restrict__ rowscale,
           float* __restrict__ Cf, __half* __restrict__ P,
           int M, int Kc, int ldA, int pLd,
           size_t aZ, size_t bZ, size_t biasZ, size_t cZ, size_t pZ) {
    extern __shared__ char smem[];
    const uint32_t sb = smem_u32(smem);
    const int tid = threadIdx.x, lane = tid & 31, wid = tid >> 5;
    const int wm = wid >> 2, wn = wid & 3;
    const int m0 = blockIdx.y * 128, n0 = blockIdx.x * 128;
    const int zz = blockIdx.z;

    A += (size_t)zz * aZ;
    B += (size_t)zz * bZ;
    if (DO_BIAS)   bias += (size_t)zz * biasZ;
    if (OUTM == 0 || OUTM == 2) Cf += (size_t)zz * cZ;
    if (OUTM >= 1) P += (size_t)zz * pZ;

    float acc[4][4][4];
#pragma unroll
    for (int a = 0; a < 4; a++)
#pragma unroll
        for (int b = 0; b < 4; b++)
#pragma unroll
            for (int c = 0; c < 4; c++) acc[a][b][c] = 0.0f;

    const int lr = tid >> 2;
    const int lc = tid & 3;

#define PREFETCH(chunk, stg) do {                                              \
        uint32_t sbase = sb + (stg) * STG;                                     \
        int k0 = (chunk) * 32;                                                 \
        _Pragma("unroll")                                                      \
        for (int i = 0; i < 2; i++) {                                          \
            int r = i * 64 + lr;                                               \
            uint32_t sw = (uint32_t)((lc ^ ((r >> 1) & 3)) * 16);              \
            cpa16(sbase + r * 64 + sw,                                         \
                  A + (size_t)(m0 + r) * ldA + k0 + lc * 8);                   \
            cpa16(sbase + 8192 + r * 64 + sw,                                  \
                  B + (size_t)(n0 + r) * ldA + k0 + lc * 8);                   \
        }                                                                      \
        asm volatile("cp.async.commit_group;" ::: "memory");                   \
    } while (0)

    const int nc = Kc >> 5;
    PREFETCH(0, 0);
    if (nc > 1) PREFETCH(1, 1);
    if (nc > 2) PREFETCH(2, 2);
    for (int ch = 0; ch < nc; ch++) {
        int stg = ch & 3;
        if (ch + 2 < nc) {
            asm volatile("cp.async.wait_group 2;" ::: "memory");
        } else if (ch + 1 < nc) {
            asm volatile("cp.async.wait_group 1;" ::: "memory");
        } else {
            asm volatile("cp.async.wait_group 0;" ::: "memory");
        }
        __syncthreads();
        if (ch + 3 < nc) PREFETCH(ch + 3, (ch + 3) & 3);

        uint32_t Abase = sb + stg * STG;
        uint32_t Bbase = Abase + 8192;
#pragma unroll
        for (int ks = 0; ks < 2; ks++) {
            int arow = wm * 64 + (lane & 15);
            int brow = wn * 32 + (lane & 15);
            int cch  = ks * 2 + (lane >> 4);
            uint32_t bf[2][4];
#pragma unroll
            for (int p = 0; p < 2; p++) {
                int r = brow + p * 16;
                ldsm4(bf[p], Bbase + r * 64 + ((cch ^ ((r >> 1) & 3)) * 16));
            }
            // Stream A fragments one at a time (register diet for 3 CTAs/SM)
#pragma unroll
            for (int mi = 0; mi < 4; mi++) {
                uint32_t af[4];
                int r = arow + mi * 16;
                ldsm4(af, Abase + r * 64 + ((cch ^ ((r >> 1) & 3)) * 16));
#pragma unroll
                for (int ni = 0; ni < 4; ni++)
                    mma16816h(acc[mi][ni], af, bf[ni >> 1][ni & 1], bf[ni >> 1][(ni & 1) + 2]);
            }
        }
        __syncthreads();
    }
#undef PREFETCH

    const int gid = lane >> 2, tg = lane & 3;
#pragma unroll
    for (int mi = 0; mi < 4; mi++) {
#pragma unroll
        for (int ni = 0; ni < 4; ni++) {
            int n = n0 + wn * 32 + ni * 8 + tg * 2;
            bool nok = (n < HID);
#pragma unroll
            for (int half = 0; half < 2; half++) {
                int m = m0 + wm * 64 + mi * 16 + gid + half * 8;
                float v0 = acc[mi][ni][half * 2 + 0];
                float v1 = acc[mi][ni][half * 2 + 1];
                bool mok = (m < M);
                if (mok && nok) {
                    if (DO_BIAS) { v0 += bias[n]; v1 += bias[n + 1]; }
                    if (DO_SSP)  { v0 = ssp_f(v0); v1 = ssp_f(v1); }
                    if (DO_RSCALE) { float rs = rowscale[m]; v0 *= rs; v1 *= rs; }
                    if (OUTM == 0) {
                        *(float2*)(Cf + (size_t)m * HID + n) = make_float2(v0, v1);
                    } else if (OUTM == 2) {
                        float* cp = Cf + (size_t)m * HID + n;
                        float2 o = *(float2*)cp;
                        v0 += o.x; v1 += o.y;
                        *(float2*)cp = make_float2(v0, v1);
                    }
                    if (OUTM == 3) {
                        *(uint32_t*)(P + (size_t)m * pLd + n) = pack_h2(v0, v1);
                    }
                } else {
                    v0 = 0.0f; v1 = 0.0f;
                }
                if (OUTM == 1 || OUTM == 2) {
                    *(uint32_t*)(P + (size_t)m * pLd + n) = pack_h2(v0, v1);
                }
            }
        }
    }
}

// ---------------------------------------------------------------------------
// CSR aggregation: de-indirected edge payload, fp16 operands, fp32 accum.
// ---------------------------------------------------------------------------
__global__ __launch_bounds__(160)
void agg_kernel(const __half* __restrict__ xh, const __half* __restrict__ tab,
                __half* __restrict__ P) {
    int c = blockIdx.x;
    int lane = threadIdx.x;
    if (lane >= HID / 4) return;
    int s = g_off[c], epd = g_off[c + 1];
    float4 acc = make_float4(0.f, 0.f, 0.f, 0.f);
    const __half* xp = xh + 4 * lane;
    const __half* tp = tab + 4 * lane;
    int2 ri = make_int2(0, 0); float f = 0.f;
    if (s < epd) { ri = g_eri[s]; f = g_efc[s]; }
    for (int j = s; j < epd; j++) {
        uint2 xu  = *(const uint2*)(xp + (size_t)ri.x * KP);
        uint2 w0u = *(const uint2*)(tp + (size_t)ri.y * HID);
        uint2 w1u = *(const uint2*)(tp + (size_t)(ri.y + 1) * HID);
        int2 rin = ri; float fn = f;
        if (j + 1 < epd) { rin = g_eri[j + 1]; fn = g_efc[j + 1]; }
        float4 xv = h4_to_f4(xu);
        float4 w0 = h4_to_f4(w0u);
        float4 w1 = h4_to_f4(w1u);
        acc.x += xv.x * fmaf(f, w1.x - w0.x, w0.x);
        acc.y += xv.y * fmaf(f, w1.y - w0.y, w0.y);
        acc.z += xv.z * fmaf(f, w1.z - w0.z, w0.z);
        acc.w += xv.w * fmaf(f, w1.w - w0.w, w0.w);
        ri = rin; f = fn;
    }
    float av[4] = {acc.x, acc.y, acc.z, acc.w};
    *(uint2*)(P + (size_t)c * KP + 4 * lane) = pack_h4(av);
}

// ---------------------------------------------------------------------------
// Launch
// ---------------------------------------------------------------------------
extern "C" void kernel_launch(void* const* d_in, const int* in_sizes, int n_in,
                              void* d_out, int out_size) {
    const int*   z      = (const int*)  d_in[0];
    const float* pos    = (const float*)d_in[1];
    const int*   ei     = (const int*)  d_in[2];
    const float* emb    = (const float*)d_in[3];
    const float* mlp1_w = (const float*)d_in[4];
    const float* mlp1_b = (const float*)d_in[5];
    const float* mlp2_w = (const float*)d_in[6];
    const float* mlp2_b = (const float*)d_in[7];
    const float* lin1_w = (const float*)d_in[8];
    const float* lin2_w = (const float*)d_in[9];
    const float* lin2_b = (const float*)d_in[10];
    const float* lin_w  = (const float*)d_in[11];
    const float* lin_b  = (const float*)d_in[12];
    float* h = (float*)d_out;

    cudaFuncSetAttribute((const void*)hgemm<1,1,0,1>, cudaFuncAttributeMaxDynamicSharedMemorySize, SMEM_BYTES);
    cudaFuncSetAttribute((const void*)hgemm<1,0,1,3>, cudaFuncAttributeMaxDynamicSharedMemorySize, SMEM_BYTES);
    cudaFuncSetAttribute((const void*)hgemm<0,0,0,0>, cudaFuncAttributeMaxDynamicSharedMemorySize, SMEM_BYTES);
    cudaFuncSetAttribute((const void*)hgemm<0,0,0,1>, cudaFuncAttributeMaxDynamicSharedMemorySize, SMEM_BYTES);
    cudaFuncSetAttribute((const void*)hgemm<1,0,0,2>, cudaFuncAttributeMaxDynamicSharedMemorySize, SMEM_BYTES);

    __half *ea, *t1, *hh, *ag, *x2, *xh, *em, *w1, *wb, *tab;
    float *xe, *Ct;
    int *cnt;
    cudaGetSymbolAddress((void**)&ea, g_ea);   cudaGetSymbolAddress((void**)&t1, g_T1);
    cudaGetSymbolAddress((void**)&hh, g_h);    cudaGetSymbolAddress((void**)&ag, g_ag);
    cudaGetSymbolAddress((void**)&x2, g_x2);   cudaGetSymbolAddress((void**)&xh, g_xh);
    cudaGetSymbolAddress((void**)&em, g_em);   cudaGetSymbolAddress((void**)&w1, g_w1);
    cudaGetSymbolAddress((void**)&wb, g_wb);   cudaGetSymbolAddress((void**)&tab, g_tab);
    cudaGetSymbolAddress((void**)&xe, g_xe);   cudaGetSymbolAddress((void**)&Ct, g_Ct);
    cudaGetSymbolAddress((void**)&cnt, g_cnt);

    // Prologue
    cudaMemsetAsync(cnt, 0, NN * sizeof(int));
    {
        dim3 gW((600 * KP / 4 + 255) / 256, 1, NITR * 4);
        cvt_wb_kernel<<<gW, 256>>>(mlp2_w, lin1_w, lin2_w, lin_w);
        dim3 gW1((600 * KP1 + 255) / 256, 1, NITR);
        cvt_w1_kernel<<<gW1, 256>>>(mlp1_w);
    }
    prologue_kernel<<<B_TAB + B_EDGE + B_EMB + B_INIT, 256>>>(z, emb, pos, ei, h);
    // Table GEMMs
    {
        dim3 gT(5, GT / 128, NITR);
        hgemm<1,1,0,1><<<gT, 256, SMEM_BYTES>>>(ea, w1,
            mlp1_b, nullptr, nullptr, t1, GT, KP1, KP1, KP,
            0, (size_t)640 * KP1, HID, 0, (size_t)GT * KP);
        hgemm<1,0,1,3><<<gT, 256, SMEM_BYTES>>>(t1, wb,
            mlp2_b, Ct, nullptr, tab, GT, KC, KP, HID,
            (size_t)GT * KP, (size_t)4 * 640 * KP, HID, 0, (size_t)GT * HID);
    }
    // Iteration-0 x via embedding table
    {
        __half* l1w0 = wb + (size_t)1 * 640 * KP;
        dim3 gZ(5, 1, 1);
        hgemm<0,0,0,0><<<gZ, 256, SMEM_BYTES>>>(em, l1w0,
            nullptr, nullptr, xe, nullptr, NZ, KC, KP, 0, 0, 0, 0, 0, 0);
        xgather_kernel<<<(int)(((long)NN * HID / 4 + 255) / 256), 256>>>(z, xe, xh);
    }
    // CSR finalize
    csr_scan_kernel<<<1, 1024>>>();
    csr_place_kernel<<<(NE + 127) / 128, 128>>>(ei);

    dim3 gN(5, NPAD / 128, 1);   // 395 tiles <= 444 slots (3 CTAs/SM) = 1 wave

    for (int it = 0; it < NITR; it++) {
        const float* l2b = lin2_b + (size_t)it * HID;
        const float* lb  = lin_b  + (size_t)it * HID;
        __half* l1w = wb + ((size_t)it * 4 + 1) * 640 * KP;
        __half* l2w = wb + ((size_t)it * 4 + 2) * 640 * KP;
        __half* lw  = wb + ((size_t)it * 4 + 3) * 640 * KP;

        if (it > 0) {
            hgemm<0,0,0,1><<<gN, 256, SMEM_BYTES>>>(hh, l1w,
                nullptr, nullptr, nullptr, xh, NN, KC, KP, KP, 0, 0, 0, 0, 0);
        }
        agg_kernel<<<NN, 160>>>(xh, tab + (size_t)it * GT * HID, ag);
        hgemm<1,1,0,1><<<gN, 256, SMEM_BYTES>>>(ag, l2w,
            l2b, nullptr, nullptr, x2, NN, KC, KP, KP, 0, 0, 0, 0, 0);
        hgemm<1,0,0,2><<<gN, 256, SMEM_BYTES>>>(x2, lw,
            lb, nullptr, h, hh, NN, KC, KP, KP, 0, 0, 0, 0, 0);
    }
}

// round 15
// speedup vs baseline: 1.1955x; 1.1955x over previous
#include <cuda_runtime.h>
#include <cuda_bf16.h>
#include <cuda_fp16.h>
#include <math.h>
#include <stdint.h>

// Problem constants
#define NN   10000
#define NE   100000
#define HID  600
#define NGS  50
#define NITR 6
#define NZ   100

#define KP   640        // plane row stride (elements)
#define KC   608        // K compute extent
#define KP1  64
#define NPAD 10112
#define GT   1024
#define DMAX 13.86f
#define STG  16384      // stage = A(8KB) + B(8KB)
#define SMEM_BYTES (4 * STG)

// ---------------------------------------------------------------------------
// Scratch
// ---------------------------------------------------------------------------
__device__ __align__(256) __half g_ea [(size_t)GT * KP1];
__device__ __align__(256) __half g_T1 [(size_t)NITR * GT * KP];
__device__ __align__(256) __half g_h  [(size_t)NPAD * KP];
__device__ __align__(256) __half g_ag [(size_t)NPAD * KP];
__device__ __align__(256) __half g_x2 [(size_t)NPAD * KP];
__device__ __align__(256) __half g_xh [(size_t)NPAD * KP];
__device__ __align__(256) __half g_em [(size_t)128 * KP];
__device__ __align__(256) __half g_w1 [(size_t)NITR * 640 * KP1];
__device__ __align__(256) __half g_wb [(size_t)NITR * 4 * 640 * KP];
__device__ __align__(256) __half g_tab[(size_t)NITR * GT * HID];
__device__ float g_xe  [(size_t)NZ * HID];
__device__ float g_Ct  [GT];
__device__ int   g_ei0 [NE];
__device__ float g_efr [NE];
__device__ int   g_cnt [NN];
__device__ int   g_off [NN + 1];
__device__ int   g_rank[NE];
// CSR-ordered edge payload (de-indirected)
__device__ int2  g_eri [NE];     // {row, i0}
__device__ float g_efc [NE];     // frac

// ---------------------------------------------------------------------------
// Helpers
// ---------------------------------------------------------------------------
__device__ __forceinline__ uint32_t smem_u32(const void* p) {
    uint32_t a;
    asm("{ .reg .u64 t; cvta.to.shared.u64 t, %1; cvt.u32.u64 %0, t; }" : "=r"(a) : "l"(p));
    return a;
}
__device__ __forceinline__ void ldsm4(uint32_t (&r)[4], uint32_t addr) {
    asm volatile("ldmatrix.sync.aligned.m8n8.x4.shared.b16 {%0,%1,%2,%3}, [%4];"
                 : "=r"(r[0]), "=r"(r[1]), "=r"(r[2]), "=r"(r[3]) : "r"(addr));
}
__device__ __forceinline__ void mma16816h(float (&d)[4], const uint32_t (&a)[4],
                                          uint32_t b0, uint32_t b1) {
    asm volatile("mma.sync.aligned.m16n8k16.row.col.f32.f16.f16.f32 "
                 "{%0,%1,%2,%3}, {%4,%5,%6,%7}, {%8,%9}, {%0,%1,%2,%3};"
                 : "+f"(d[0]), "+f"(d[1]), "+f"(d[2]), "+f"(d[3])
                 : "r"(a[0]), "r"(a[1]), "r"(a[2]), "r"(a[3]), "r"(b0), "r"(b1));
}
__device__ __forceinline__ void cpa16(uint32_t dst, const void* src) {
    asm volatile("cp.async.cg.shared.global [%0], [%1], 16;" :: "r"(dst), "l"(src));
}
__device__ __forceinline__ float ssp_f(float v) {
    float av = fabsf(v);
    return fmaxf(v, 0.0f) + log1pf(expf(-av)) - 0.69314718055994530942f;
}
__device__ __forceinline__ uint32_t pack_h2(float a, float b) {
    __half2 p = __floats2half2_rn(a, b);
    return *(uint32_t*)&p;
}
__device__ __forceinline__ uint2 pack_h4(const float* v) {
    uint2 u;
    u.x = pack_h2(v[0], v[1]);
    u.y = pack_h2(v[2], v[3]);
    return u;
}
__device__ __forceinline__ float4 h4_to_f4(uint2 u) {
    float2 a = __half22float2(*(__half2*)&u.x);
    float2 b = __half22float2(*(__half2*)&u.y);
    return make_float4(a.x, a.y, b.x, b.y);
}

// ---------------------------------------------------------------------------
// Fused prologue
// ---------------------------------------------------------------------------
#define B_TAB  (GT / 256)
#define B_EDGE ((NE + 255) / 256)
#define B_EMB  ((128 * KP) / 1024)
#define B_INIT ((NN * KP) / 1024)

__global__ void prologue_kernel(const int* __restrict__ z, const float* __restrict__ emb,
                                const float* __restrict__ pos, const int* __restrict__ ei,
                                float* __restrict__ hout) {
    int bx = blockIdx.x;
    if (bx < B_TAB) {
        int g = bx * 256 + threadIdx.x;
        float d = (float)g * (DMAX / (float)(GT - 1));
        g_Ct[g] = 0.5f * (cosf(d * (float)(M_PI / 10.0)) + 1.0f);
        const float step  = 10.0f / 49.0f;
        const float coeff = -0.5f / (step * step);
        __half* eh = g_ea + (size_t)g * KP1;
#pragma unroll 8
        for (int k = 0; k < KP1; k++) {
            float v = 0.0f;
            if (k < NGS) { float t = d - step * (float)k; v = expf(coeff * t * t); }
            eh[k] = __float2half_rn(v);
        }
    } else if (bx < B_TAB + B_EDGE) {
        int e = (bx - B_TAB) * 256 + threadIdx.x;
        if (e >= NE) return;
        int r = ei[e], c = ei[NE + e];
        float dx = pos[3*r+0] - pos[3*c+0];
        float dy = pos[3*r+1] - pos[3*c+1];
        float dz = pos[3*r+2] - pos[3*c+2];
        float d = sqrtf(dx*dx + dy*dy + dz*dz);
        float t = d * ((float)(GT - 1) / DMAX);
        int i0 = (int)t;
        if (i0 > GT - 2) i0 = GT - 2;
        g_ei0[e] = i0;
        g_efr[e] = t - (float)i0;
        g_rank[e] = atomicAdd(&g_cnt[c], 1);
    } else if (bx < B_TAB + B_EDGE + B_EMB) {
        long i = ((long)(bx - B_TAB - B_EDGE) * 256 + threadIdx.x) * 4;
        int r = (int)(i / KP), k = (int)(i - (long)r * KP);
        float v[4] = {0.f, 0.f, 0.f, 0.f};
        if (r < NZ && k < HID) *(float4*)v = *(const float4*)(emb + (size_t)r * HID + k);
        *(uint2*)(g_em + i) = pack_h4(v);
    } else {
        long i = ((long)(bx - B_TAB - B_EDGE - B_EMB) * 256 + threadIdx.x) * 4;
        int n = (int)(i / KP), k = (int)(i - (long)n * KP);
        float v[4] = {0.f, 0.f, 0.f, 0.f};
        if (k < HID) {
            *(float4*)v = *(const float4*)(emb + (size_t)z[n] * HID + k);
            *(float4*)(hout + (size_t)n * HID + k) = *(float4*)v;
        }
        *(uint2*)(g_h + i) = pack_h4(v);
    }
}

// Exclusive scan of g_cnt -> g_off
__global__ __launch_bounds__(1024)
void csr_scan_kernel() {
    __shared__ int part[1024];
    int t = threadIdx.x;
    int base = t * 10;
    int loc[10];
    int s = 0;
#pragma unroll
    for (int i = 0; i < 10; i++) {
        int idx = base + i;
        loc[i] = s;
        s += (idx < NN) ? g_cnt[idx] : 0;
    }
    part[t] = s;
    __syncthreads();
    for (int off = 1; off < 1024; off <<= 1) {
        int v = (t >= off) ? part[t - off] : 0;
        __syncthreads();
        if (t >= off) part[t] += v;
        __syncthreads();
    }
    int pre = (t > 0) ? part[t - 1] : 0;
#pragma unroll
    for (int i = 0; i < 10; i++) {
        int idx = base + i;
        if (idx < NN) g_off[idx] = pre + loc[i];
    }
    if (t == 1023) g_off[NN] = part[1023];
}

// Place edges into CSR order with de-indirected payload {row, i0, frac}
__global__ void csr_place_kernel(const int* __restrict__ ei) {
    int e = blockIdx.x * blockDim.x + threadIdx.x;
    if (e >= NE) return;
    int c = ei[NE + e];
    int j = g_off[c] + g_rank[e];
    g_eri[j] = make_int2(ei[e], g_ei0[e]);
    g_efc[j] = g_efr[e];
}

// Batched 4-wide convert of 24 HID x HID weights
__global__ void cvt_wb_kernel(const float* __restrict__ w2, const float* __restrict__ l1,
                              const float* __restrict__ l2, const float* __restrict__ lw) {
    int zz = blockIdx.z;
    int wix = zz & 3, it = zz >> 2;
    const float* src = ((wix == 0) ? w2 : (wix == 1) ? l1 : (wix == 2) ? l2 : lw)
                       + (size_t)it * HID * HID;
    __half* dh = g_wb + (size_t)zz * 640 * KP;
    long i = ((long)blockIdx.x * blockDim.x + threadIdx.x) * 4;
    if (i >= (long)600 * KP) return;
    int r = (int)(i / KP), k = (int)(i - (long)r * KP);
    float v[4] = {0.f, 0.f, 0.f, 0.f};
    if (k < HID) *(float4*)v = *(const float4*)(src + (size_t)r * HID + k);
    *(uint2*)(dh + i) = pack_h4(v);
}

__global__ void cvt_w1_kernel(const float* __restrict__ w1) {
    int it = blockIdx.z;
    const float* src = w1 + (size_t)it * HID * NGS;
    __half* dh = g_w1 + (size_t)it * 640 * KP1;
    long i = blockIdx.x * (long)blockDim.x + threadIdx.x;
    if (i >= (long)600 * KP1) return;
    int r = (int)(i / KP1), k = (int)(i - (long)r * KP1);
    float v = (k < NGS) ? src[(size_t)r * NGS + k] : 0.0f;
    dh[i] = __float2half_rn(v);
}

// x plane[n] = fp16(xe[z[n]])
__global__ void xgather_kernel(const int* __restrict__ z, const float* __restrict__ xe,
                               __half* __restrict__ xh) {
    long i = ((long)blockIdx.x * blockDim.x + threadIdx.x) * 4;
    if (i >= (long)NN * HID) return;
    int n = (int)(i / HID), k = (int)(i - (long)n * HID);
    float v[4];
    *(float4*)v = *(const float4*)(xe + (size_t)z[n] * HID + k);
    *(uint2*)(xh + (size_t)n * KP + k) = pack_h4(v);
}

// ---------------------------------------------------------------------------
// fp16 HMMA GEMM, 128x128 tile, 2 CTAs/SM (R13 config), 4-stage pipeline,
// hoisted swizzled row bases.
// OUTM: 0 fp32 Cf; 1 fp16 plane (zero-pads); 2 fp32 residual + plane; 3 fp16 valid-only
// ---------------------------------------------------------------------------
template <int DO_BIAS, int DO_SSP, int DO_RSCALE, int OUTM>
__global__ __launch_bounds__(256, 2)
void hgemm(const __half* __restrict__ A, const __half* __restrict__ B,
           const float* __restrict__ bias, const float* __restrict__ rowscale,
           float* __restrict__ Cf, __half* __restrict__ P,
           int M, int Kc, int ldA, int pLd,
           size_t aZ, size_t bZ, size_t biasZ, size_t cZ, size_t pZ) {
    extern __shared__ char smem[];
    const uint32_t sb = smem_u32(smem);
    const int tid = threadIdx.x, lane = tid & 31, wid = tid >> 5;
    const int wm = wid >> 2, wn = wid & 3;
    const int m0 = blockIdx.y * 128, n0 = blockIdx.x * 128;
    const int zz = blockIdx.z;

    A += (size_t)zz * aZ;
    B += (size_t)zz * bZ;
    if (DO_BIAS)   bias += (size_t)zz * biasZ;
    if (OUTM == 0 || OUTM == 2) Cf += (size_t)zz * cZ;
    if (OUTM >= 1) P += (size_t)zz * pZ;

    float acc[4][4][4];
#pragma unroll
    for (int a = 0; a < 4; a++)
#pragma unroll
        for (int b = 0; b < 4; b++)
#pragma unroll
            for (int c = 0; c < 4; c++) acc[a][b][c] = 0.0f;

    const int lr = tid >> 2;
    const int lc = tid & 3;

    // Hoisted per-warp ldsm row offsets (within a stage):
    // off(r, cch) = r*64 + ((cch ^ ((r>>1)&3)) * 16)
    //            = [r*64 + (((r>>1)&3) * 16)]  XOR  (cch * 16)   since XOR of
    //              2-bit fields scaled by 16 == addition-free bit toggle.
    const int arow = wm * 64 + (lane & 15);
    const int brow = wn * 32 + (lane & 15);
    uint32_t abase[4], bbase[2];
#pragma unroll
    for (int mi = 0; mi < 4; mi++) {
        int r = arow + mi * 16;
        abase[mi] = (uint32_t)(r * 64 + (((r >> 1) & 3) * 16));
    }
#pragma unroll
    for (int p = 0; p < 2; p++) {
        int r = brow + p * 16;
        bbase[p] = (uint32_t)(r * 64 + (((r >> 1) & 3) * 16));
    }

#define PREFETCH(chunk, stg) do {                                              \
        uint32_t sbase = sb + (stg) * STG;                                     \
        int k0 = (chunk) * 32;                                                 \
        _Pragma("unroll")                                                      \
        for (int i = 0; i < 2; i++) {                                          \
            int r = i * 64 + lr;                                               \
            uint32_t sw = (uint32_t)((lc ^ ((r >> 1) & 3)) * 16);              \
            cpa16(sbase + r * 64 + sw,                                         \
                  A + (size_t)(m0 + r) * ldA + k0 + lc * 8);                   \
            cpa16(sbase + 8192 + r * 64 + sw,                                  \
                  B + (size_t)(n0 + r) * ldA + k0 + lc * 8);                   \
        }                                                                      \
        asm volatile("cp.async.commit_group;" ::: "memory");                   \
    } while (0)

    const int nc = Kc >> 5;
    PREFETCH(0, 0);
    if (nc > 1) PREFETCH(1, 1);
    if (nc > 2) PREFETCH(2, 2);
    for (int ch = 0; ch < nc; ch++) {
        int stg = ch & 3;
        if (ch + 2 < nc) {
            asm volatile("cp.async.wait_group 2;" ::: "memory");
        } else if (ch + 1 < nc) {
            asm volatile("cp.async.wait_group 1;" ::: "memory");
        } else {
            asm volatile("cp.async.wait_group 0;" ::: "memory");
        }
        __syncthreads();
        if (ch + 3 < nc) PREFETCH(ch + 3, (ch + 3) & 3);

        uint32_t Abase = sb + stg * STG;
        uint32_t Bbase = Abase + 8192;
#pragma unroll
        for (int ks = 0; ks < 2; ks++) {
            uint32_t cx = (uint32_t)((ks * 2 + (lane >> 4)) * 16);
            uint32_t af[4][4], bf[2][4];
#pragma unroll
            for (int p = 0; p < 2; p++)
                ldsm4(bf[p], Bbase + (bbase[p] ^ cx));
#pragma unroll
            for (int mi = 0; mi < 4; mi++)
                ldsm4(af[mi], Abase + (abase[mi] ^ cx));
#pragma unroll
            for (int mi = 0; mi < 4; mi++)
#pragma unroll
                for (int ni = 0; ni < 4; ni++)
                    mma16816h(acc[mi][ni], af[mi], bf[ni >> 1][ni & 1], bf[ni >> 1][(ni & 1) + 2]);
        }
        __syncthreads();
    }
#undef PREFETCH

    const int gid = lane >> 2, tg = lane & 3;
#pragma unroll
    for (int mi = 0; mi < 4; mi++) {
#pragma unroll
        for (int ni = 0; ni < 4; ni++) {
            int n = n0 + wn * 32 + ni * 8 + tg * 2;
            bool nok = (n < HID);
#pragma unroll
            for (int half = 0; half < 2; half++) {
                int m = m0 + wm * 64 + mi * 16 + gid + half * 8;
                float v0 = acc[mi][ni][half * 2 + 0];
                float v1 = acc[mi][ni][half * 2 + 1];
                bool mok = (m < M);
                if (mok && nok) {
                    if (DO_BIAS) { v0 += bias[n]; v1 += bias[n + 1]; }
                    if (DO_SSP)  { v0 = ssp_f(v0); v1 = ssp_f(v1); }
                    if (DO_RSCALE) { float rs = rowscale[m]; v0 *= rs; v1 *= rs; }
                    if (OUTM == 0) {
                        *(float2*)(Cf + (size_t)m * HID + n) = make_float2(v0, v1);
                    } else if (OUTM == 2) {
                        float* cp = Cf + (size_t)m * HID + n;
                        float2 o = *(float2*)cp;
                        v0 += o.x; v1 += o.y;
                        *(float2*)cp = make_float2(v0, v1);
                    }
                    if (OUTM == 3) {
                        *(uint32_t*)(P + (size_t)m * pLd + n) = pack_h2(v0, v1);
                    }
                } else {
                    v0 = 0.0f; v1 = 0.0f;
                }
                if (OUTM == 1 || OUTM == 2) {
                    *(uint32_t*)(P + (size_t)m * pLd + n) = pack_h2(v0, v1);
                }
            }
        }
    }
}

// ---------------------------------------------------------------------------
// CSR aggregation: de-indirected payload, fp16 operands, fp32 accum.
// ---------------------------------------------------------------------------
__global__ __launch_bounds__(160)
void agg_kernel(const __half* __restrict__ xh, const __half* __restrict__ tab,
                __half* __restrict__ P) {
    int c = blockIdx.x;
    int lane = threadIdx.x;
    if (lane >= HID / 4) return;
    int s = g_off[c], epd = g_off[c + 1];
    float4 acc = make_float4(0.f, 0.f, 0.f, 0.f);
    const __half* xp = xh + 4 * lane;
    const __half* tp = tab + 4 * lane;
    int2 ri = make_int2(0, 0); float f = 0.f;
    if (s < epd) { ri = g_eri[s]; f = g_efc[s]; }
    for (int j = s; j < epd; j++) {
        uint2 xu  = *(const uint2*)(xp + (size_t)ri.x * KP);
        uint2 w0u = *(const uint2*)(tp + (size_t)ri.y * HID);
        uint2 w1u = *(const uint2*)(tp + (size_t)(ri.y + 1) * HID);
        int2 rin = ri; float fn = f;
        if (j + 1 < epd) { rin = g_eri[j + 1]; fn = g_efc[j + 1]; }
        float4 xv = h4_to_f4(xu);
        float4 w0 = h4_to_f4(w0u);
        float4 w1 = h4_to_f4(w1u);
        acc.x += xv.x * fmaf(f, w1.x - w0.x, w0.x);
        acc.y += xv.y * fmaf(f, w1.y - w0.y, w0.y);
        acc.z += xv.z * fmaf(f, w1.z - w0.z, w0.z);
        acc.w += xv.w * fmaf(f, w1.w - w0.w, w0.w);
        ri = rin; f = fn;
    }
    float av[4] = {acc.x, acc.y, acc.z, acc.w};
    *(uint2*)(P + (size_t)c * KP + 4 * lane) = pack_h4(av);
}

// ---------------------------------------------------------------------------
// Launch
// ---------------------------------------------------------------------------
extern "C" void kernel_launch(void* const* d_in, const int* in_sizes, int n_in,
                              void* d_out, int out_size) {
    const int*   z      = (const int*)  d_in[0];
    const float* pos    = (const float*)d_in[1];
    const int*   ei     = (const int*)  d_in[2];
    const float* emb    = (const float*)d_in[3];
    const float* mlp1_w = (const float*)d_in[4];
    const float* mlp1_b = (const float*)d_in[5];
    const float* mlp2_w = (const float*)d_in[6];
    const float* mlp2_b = (const float*)d_in[7];
    const float* lin1_w = (const float*)d_in[8];
    const float* lin2_w = (const float*)d_in[9];
    const float* lin2_b = (const float*)d_in[10];
    const float* lin_w  = (const float*)d_in[11];
    const float* lin_b  = (const float*)d_in[12];
    float* h = (float*)d_out;

    cudaFuncSetAttribute((const void*)hgemm<1,1,0,1>, cudaFuncAttributeMaxDynamicSharedMemorySize, SMEM_BYTES);
    cudaFuncSetAttribute((const void*)hgemm<1,0,1,3>, cudaFuncAttributeMaxDynamicSharedMemorySize, SMEM_BYTES);
    cudaFuncSetAttribute((const void*)hgemm<0,0,0,0>, cudaFuncAttributeMaxDynamicSharedMemorySize, SMEM_BYTES);
    cudaFuncSetAttribute((const void*)hgemm<0,0,0,1>, cudaFuncAttributeMaxDynamicSharedMemorySize, SMEM_BYTES);
    cudaFuncSetAttribute((const void*)hgemm<1,0,0,2>, cudaFuncAttributeMaxDynamicSharedMemorySize, SMEM_BYTES);

    __half *ea, *t1, *hh, *ag, *x2, *xh, *em, *w1, *wb, *tab;
    float *xe, *Ct;
    int *cnt;
    cudaGetSymbolAddress((void**)&ea, g_ea);   cudaGetSymbolAddress((void**)&t1, g_T1);
    cudaGetSymbolAddress((void**)&hh, g_h);    cudaGetSymbolAddress((void**)&ag, g_ag);
    cudaGetSymbolAddress((void**)&x2, g_x2);   cudaGetSymbolAddress((void**)&xh, g_xh);
    cudaGetSymbolAddress((void**)&em, g_em);   cudaGetSymbolAddress((void**)&w1, g_w1);
    cudaGetSymbolAddress((void**)&wb, g_wb);   cudaGetSymbolAddress((void**)&tab, g_tab);
    cudaGetSymbolAddress((void**)&xe, g_xe);   cudaGetSymbolAddress((void**)&Ct, g_Ct);
    cudaGetSymbolAddress((void**)&cnt, g_cnt);

    // Prologue
    cudaMemsetAsync(cnt, 0, NN * sizeof(int));
    {
        dim3 gW((600 * KP / 4 + 255) / 256, 1, NITR * 4);
        cvt_wb_kernel<<<gW, 256>>>(mlp2_w, lin1_w, lin2_w, lin_w);
        dim3 gW1((600 * KP1 + 255) / 256, 1, NITR);
        cvt_w1_kernel<<<gW1, 256>>>(mlp1_w);
    }
    prologue_kernel<<<B_TAB + B_EDGE + B_EMB + B_INIT, 256>>>(z, emb, pos, ei, h);
    // Table GEMMs
    {
        dim3 gT(5, GT / 128, NITR);
        hgemm<1,1,0,1><<<gT, 256, SMEM_BYTES>>>(ea, w1,
            mlp1_b, nullptr, nullptr, t1, GT, KP1, KP1, KP,
            0, (size_t)640 * KP1, HID, 0, (size_t)GT * KP);
        hgemm<1,0,1,3><<<gT, 256, SMEM_BYTES>>>(t1, wb,
            mlp2_b, Ct, nullptr, tab, GT, KC, KP, HID,
            (size_t)GT * KP, (size_t)4 * 640 * KP, HID, 0, (size_t)GT * HID);
    }
    // Iteration-0 x via embedding table
    {
        __half* l1w0 = wb + (size_t)1 * 640 * KP;
        dim3 gZ(5, 1, 1);
        hgemm<0,0,0,0><<<gZ, 256, SMEM_BYTES>>>(em, l1w0,
            nullptr, nullptr, xe, nullptr, NZ, KC, KP, 0, 0, 0, 0, 0, 0);
        xgather_kernel<<<(int)(((long)NN * HID / 4 + 255) / 256), 256>>>(z, xe, xh);
    }
    // CSR finalize
    csr_scan_kernel<<<1, 1024>>>();
    csr_place_kernel<<<(NE + 127) / 128, 128>>>(ei);

    dim3 gN(5, NPAD / 128, 1);

    for (int it = 0; it < NITR; it++) {
        const float* l2b = lin2_b + (size_t)it * HID;
        const float* lb  = lin_b  + (size_t)it * HID;
        __half* l1w = wb + ((size_t)it * 4 + 1) * 640 * KP;
        __half* l2w = wb + ((size_t)it * 4 + 2) * 640 * KP;
        __half* lw  = wb + ((size_t)it * 4 + 3) * 640 * KP;

        if (it > 0) {
            hgemm<0,0,0,1><<<gN, 256, SMEM_BYTES>>>(hh, l1w,
                nullptr, nullptr, nullptr, xh, NN, KC, KP, KP, 0, 0, 0, 0, 0);
        }
        agg_kernel<<<NN, 160>>>(xh, tab + (size_t)it * GT * HID, ag);
        hgemm<1,1,0,1><<<gN, 256, SMEM_BYTES>>>(ag, l2w,
            l2b, nullptr, nullptr, x2, NN, KC, KP, KP, 0, 0, 0, 0, 0);
        hgemm<1,0,0,2><<<gN, 256, SMEM_BYTES>>>(x2, lw,
            lb, nullptr, h, hh, NN, KC, KP, KP, 0, 0, 0, 0, 0);
    }
}

// round 16
// speedup vs baseline: 1.2052x; 1.0081x over previous
#include <cuda_runtime.h>
#include <cuda_bf16.h>
#include <cuda_fp16.h>
#include <math.h>
#include <stdint.h>

// Problem constants
#define NN   10000
#define NE   100000
#define HID  600
#define NGS  50
#define NITR 6
#define NZ   100

#define KP   640        // plane row stride (elements)
#define KC   608        // K compute extent
#define KP1  64
#define NPAD 10112
#define GT   1024
#define DMAX 13.86f
// 96x128 tile: stage = A(96*64=6144) + B(128*64=8192) = 14336 B
#define STG  14336
#define SMEM_BYTES (4 * STG)
#define MT96(M) (((M) + 95) / 96)

// ---------------------------------------------------------------------------
// Scratch
// ---------------------------------------------------------------------------
__device__ __align__(256) __half g_ea [(size_t)(GT + 32) * KP1];   // +32 pad rows
__device__ __align__(256) __half g_T1 [(size_t)NITR * GT * KP + 96 * KP]; // tail pad
__device__ __align__(256) __half g_h  [(size_t)NPAD * KP];
__device__ __align__(256) __half g_ag [(size_t)NPAD * KP];
__device__ __align__(256) __half g_x2 [(size_t)NPAD * KP];
__device__ __align__(256) __half g_xh [(size_t)NPAD * KP];
__device__ __align__(256) __half g_em [(size_t)192 * KP];          // padded rows
__device__ __align__(256) __half g_w1 [(size_t)NITR * 640 * KP1];
__device__ __align__(256) __half g_wb [(size_t)NITR * 4 * 640 * KP];
__device__ __align__(256) __half g_tab[(size_t)NITR * GT * HID];
__device__ float g_xe  [(size_t)NZ * HID];
__device__ float g_Ct  [GT];
__device__ int   g_ei0 [NE];
__device__ float g_efr [NE];
__device__ int   g_cnt [NN];
__device__ int   g_off [NN + 1];
__device__ int   g_rank[NE];
__device__ int2  g_eri [NE];     // {row, i0} in CSR order
__device__ float g_efc [NE];     // frac in CSR order

// ---------------------------------------------------------------------------
// Helpers
// ---------------------------------------------------------------------------
__device__ __forceinline__ uint32_t smem_u32(const void* p) {
    uint32_t a;
    asm("{ .reg .u64 t; cvta.to.shared.u64 t, %1; cvt.u32.u64 %0, t; }" : "=r"(a) : "l"(p));
    return a;
}
__device__ __forceinline__ void ldsm4(uint32_t (&r)[4], uint32_t addr) {
    asm volatile("ldmatrix.sync.aligned.m8n8.x4.shared.b16 {%0,%1,%2,%3}, [%4];"
                 : "=r"(r[0]), "=r"(r[1]), "=r"(r[2]), "=r"(r[3]) : "r"(addr));
}
__device__ __forceinline__ void mma16816h(float (&d)[4], const uint32_t (&a)[4],
                                          uint32_t b0, uint32_t b1) {
    asm volatile("mma.sync.aligned.m16n8k16.row.col.f32.f16.f16.f32 "
                 "{%0,%1,%2,%3}, {%4,%5,%6,%7}, {%8,%9}, {%0,%1,%2,%3};"
                 : "+f"(d[0]), "+f"(d[1]), "+f"(d[2]), "+f"(d[3])
                 : "r"(a[0]), "r"(a[1]), "r"(a[2]), "r"(a[3]), "r"(b0), "r"(b1));
}
__device__ __forceinline__ void cpa16(uint32_t dst, const void* src) {
    asm volatile("cp.async.cg.shared.global [%0], [%1], 16;" :: "r"(dst), "l"(src));
}
__device__ __forceinline__ float ssp_f(float v) {
    float av = fabsf(v);
    return fmaxf(v, 0.0f) + log1pf(expf(-av)) - 0.69314718055994530942f;
}
__device__ __forceinline__ uint32_t pack_h2(float a, float b) {
    __half2 p = __floats2half2_rn(a, b);
    return *(uint32_t*)&p;
}
__device__ __forceinline__ uint2 pack_h4(const float* v) {
    uint2 u;
    u.x = pack_h2(v[0], v[1]);
    u.y = pack_h2(v[2], v[3]);
    return u;
}
__device__ __forceinline__ float4 h4_to_f4(uint2 u) {
    float2 a = __half22float2(*(__half2*)&u.x);
    float2 b = __half22float2(*(__half2*)&u.y);
    return make_float4(a.x, a.y, b.x, b.y);
}

// ---------------------------------------------------------------------------
// Fused prologue
// ---------------------------------------------------------------------------
#define B_TAB  (GT / 256)
#define B_EDGE ((NE + 255) / 256)
#define B_EMB  ((128 * KP) / 1024)
#define B_INIT ((NN * KP) / 1024)

__global__ void prologue_kernel(const int* __restrict__ z, const float* __restrict__ emb,
                                const float* __restrict__ pos, const int* __restrict__ ei,
                                float* __restrict__ hout) {
    int bx = blockIdx.x;
    if (bx < B_TAB) {
        int g = bx * 256 + threadIdx.x;
        float d = (float)g * (DMAX / (float)(GT - 1));
        g_Ct[g] = 0.5f * (cosf(d * (float)(M_PI / 10.0)) + 1.0f);
        const float step  = 10.0f / 49.0f;
        const float coeff = -0.5f / (step * step);
        __half* eh = g_ea + (size_t)g * KP1;
#pragma unroll 8
        for (int k = 0; k < KP1; k++) {
            float v = 0.0f;
            if (k < NGS) { float t = d - step * (float)k; v = expf(coeff * t * t); }
            eh[k] = __float2half_rn(v);
        }
    } else if (bx < B_TAB + B_EDGE) {
        int e = (bx - B_TAB) * 256 + threadIdx.x;
        if (e >= NE) return;
        int r = ei[e], c = ei[NE + e];
        float dx = pos[3*r+0] - pos[3*c+0];
        float dy = pos[3*r+1] - pos[3*c+1];
        float dz = pos[3*r+2] - pos[3*c+2];
        float d = sqrtf(dx*dx + dy*dy + dz*dz);
        float t = d * ((float)(GT - 1) / DMAX);
        int i0 = (int)t;
        if (i0 > GT - 2) i0 = GT - 2;
        g_ei0[e] = i0;
        g_efr[e] = t - (float)i0;
        g_rank[e] = atomicAdd(&g_cnt[c], 1);
    } else if (bx < B_TAB + B_EDGE + B_EMB) {
        long i = ((long)(bx - B_TAB - B_EDGE) * 256 + threadIdx.x) * 4;
        int r = (int)(i / KP), k = (int)(i - (long)r * KP);
        float v[4] = {0.f, 0.f, 0.f, 0.f};
        if (r < NZ && k < HID) *(float4*)v = *(const float4*)(emb + (size_t)r * HID + k);
        *(uint2*)(g_em + i) = pack_h4(v);
    } else {
        long i = ((long)(bx - B_TAB - B_EDGE - B_EMB) * 256 + threadIdx.x) * 4;
        int n = (int)(i / KP), k = (int)(i - (long)n * KP);
        float v[4] = {0.f, 0.f, 0.f, 0.f};
        if (k < HID) {
            *(float4*)v = *(const float4*)(emb + (size_t)z[n] * HID + k);
            *(float4*)(hout + (size_t)n * HID + k) = *(float4*)v;
        }
        *(uint2*)(g_h + i) = pack_h4(v);
    }
}

// Exclusive scan of g_cnt -> g_off
__global__ __launch_bounds__(1024)
void csr_scan_kernel() {
    __shared__ int part[1024];
    int t = threadIdx.x;
    int base = t * 10;
    int loc[10];
    int s = 0;
#pragma unroll
    for (int i = 0; i < 10; i++) {
        int idx = base + i;
        loc[i] = s;
        s += (idx < NN) ? g_cnt[idx] : 0;
    }
    part[t] = s;
    __syncthreads();
    for (int off = 1; off < 1024; off <<= 1) {
        int v = (t >= off) ? part[t - off] : 0;
        __syncthreads();
        if (t >= off) part[t] += v;
        __syncthreads();
    }
    int pre = (t > 0) ? part[t - 1] : 0;
#pragma unroll
    for (int i = 0; i < 10; i++) {
        int idx = base + i;
        if (idx < NN) g_off[idx] = pre + loc[i];
    }
    if (t == 1023) g_off[NN] = part[1023];
}

__global__ void csr_place_kernel(const int* __restrict__ ei) {
    int e = blockIdx.x * blockDim.x + threadIdx.x;
    if (e >= NE) return;
    int c = ei[NE + e];
    int j = g_off[c] + g_rank[e];
    g_eri[j] = make_int2(ei[e], g_ei0[e]);
    g_efc[j] = g_efr[e];
}

// Batched 4-wide convert of 24 HID x HID weights
__global__ void cvt_wb_kernel(const float* __restrict__ w2, const float* __restrict__ l1,
                              const float* __restrict__ l2, const float* __restrict__ lw) {
    int zz = blockIdx.z;
    int wix = zz & 3, it = zz >> 2;
    const float* src = ((wix == 0) ? w2 : (wix == 1) ? l1 : (wix == 2) ? l2 : lw)
                       + (size_t)it * HID * HID;
    __half* dh = g_wb + (size_t)zz * 640 * KP;
    long i = ((long)blockIdx.x * blockDim.x + threadIdx.x) * 4;
    if (i >= (long)600 * KP) return;
    int r = (int)(i / KP), k = (int)(i - (long)r * KP);
    float v[4] = {0.f, 0.f, 0.f, 0.f};
    if (k < HID) *(float4*)v = *(const float4*)(src + (size_t)r * HID + k);
    *(uint2*)(dh + i) = pack_h4(v);
}

__global__ void cvt_w1_kernel(const float* __restrict__ w1) {
    int it = blockIdx.z;
    const float* src = w1 + (size_t)it * HID * NGS;
    __half* dh = g_w1 + (size_t)it * 640 * KP1;
    long i = blockIdx.x * (long)blockDim.x + threadIdx.x;
    if (i >= (long)600 * KP1) return;
    int r = (int)(i / KP1), k = (int)(i - (long)r * KP1);
    float v = (k < NGS) ? src[(size_t)r * NGS + k] : 0.0f;
    dh[i] = __float2half_rn(v);
}

// x plane[n] = fp16(xe[z[n]])
__global__ void xgather_kernel(const int* __restrict__ z, const float* __restrict__ xe,
                               __half* __restrict__ xh) {
    long i = ((long)blockIdx.x * blockDim.x + threadIdx.x) * 4;
    if (i >= (long)NN * HID) return;
    int n = (int)(i / HID), k = (int)(i - (long)n * HID);
    float v[4];
    *(float4*)v = *(const float4*)(xe + (size_t)z[n] * HID + k);
    *(uint2*)(xh + (size_t)n * KP + k) = pack_h4(v);
}

// ---------------------------------------------------------------------------
// fp16 HMMA GEMM, 96x128 tile, 2 CTAs/SM, 4-stage pipeline, hoisted bases.
// Warp grid 2x4, warp tile 48x32 (acc[3][4][4] = 48 regs).
// OUTM: 0 fp32 Cf; 1 fp16 plane (zero-pads, guarded by Mplane);
//       2 fp32 residual + plane; 3 fp16 valid-only
// ---------------------------------------------------------------------------
template <int DO_BIAS, int DO_SSP, int DO_RSCALE, int OUTM>
__global__ __launch_bounds__(256, 2)
void hgemm(const __half* __restrict__ A, const __half* __restrict__ B,
           const float* __restrict__ bias, const float* __restrict__ rowscale,
           float* __restrict__ Cf, __half* __restrict__ P,
           int M, int Mplane, int Kc, int ldA, int pLd,
           size_t aZ, size_t bZ, size_t biasZ, size_t cZ, size_t pZ) {
    extern __shared__ char smem[];
    const uint32_t sb = smem_u32(smem);
    const int tid = threadIdx.x, lane = tid & 31, wid = tid >> 5;
    const int wm = wid >> 2, wn = wid & 3;
    const int m0 = blockIdx.y * 96, n0 = blockIdx.x * 128;
    const int zz = blockIdx.z;

    A += (size_t)zz * aZ;
    B += (size_t)zz * bZ;
    if (DO_BIAS)   bias += (size_t)zz * biasZ;
    if (OUTM == 0 || OUTM == 2) Cf += (size_t)zz * cZ;
    if (OUTM >= 1) P += (size_t)zz * pZ;

    float acc[3][4][4];
#pragma unroll
    for (int a = 0; a < 3; a++)
#pragma unroll
        for (int b = 0; b < 4; b++)
#pragma unroll
            for (int c = 0; c < 4; c++) acc[a][b][c] = 0.0f;

    const int lr = tid >> 2;
    const int lc = tid & 3;

    // Hoisted ldsm row bases: off(r,cch) = [r*64 + ((r>>1)&3)*16] XOR (cch*16)
    const int arow = wm * 48 + (lane & 15);
    const int brow = wn * 32 + (lane & 15);
    uint32_t abase[3], bbase[2];
#pragma unroll
    for (int mi = 0; mi < 3; mi++) {
        int r = arow + mi * 16;
        abase[mi] = (uint32_t)(r * 64 + (((r >> 1) & 3) * 16));
    }
#pragma unroll
    for (int p = 0; p < 2; p++) {
        int r = brow + p * 16;
        bbase[p] = (uint32_t)(r * 64 + (((r >> 1) & 3) * 16));
    }

#define PREFETCH(chunk, stg) do {                                              \
        uint32_t sbase = sb + (stg) * STG;                                     \
        int k0 = (chunk) * 32;                                                 \
        _Pragma("unroll")                                                      \
        for (int i = 0; i < 2; i++) {                                          \
            int r = i * 64 + lr;                                               \
            uint32_t sw = (uint32_t)((lc ^ ((r >> 1) & 3)) * 16);              \
            if (r < 96)                                                        \
                cpa16(sbase + r * 64 + sw,                                     \
                      A + (size_t)(m0 + r) * ldA + k0 + lc * 8);               \
            cpa16(sbase + 6144 + r * 64 + sw,                                  \
                  B + (size_t)(n0 + r) * ldA + k0 + lc * 8);                   \
        }                                                                      \
        asm volatile("cp.async.commit_group;" ::: "memory");                   \
    } while (0)

    const int nc = Kc >> 5;
    PREFETCH(0, 0);
    if (nc > 1) PREFETCH(1, 1);
    if (nc > 2) PREFETCH(2, 2);
    for (int ch = 0; ch < nc; ch++) {
        int stg = ch & 3;
        if (ch + 2 < nc) {
            asm volatile("cp.async.wait_group 2;" ::: "memory");
        } else if (ch + 1 < nc) {
            asm volatile("cp.async.wait_group 1;" ::: "memory");
        } else {
            asm volatile("cp.async.wait_group 0;" ::: "memory");
        }
        __syncthreads();
        if (ch + 3 < nc) PREFETCH(ch + 3, (ch + 3) & 3);

        uint32_t Abase = sb + stg * STG;
        uint32_t Bbase = Abase + 6144;
#pragma unroll
        for (int ks = 0; ks < 2; ks++) {
            uint32_t cx = (uint32_t)((ks * 2 + (lane >> 4)) * 16);
            uint32_t af[3][4], bf[2][4];
#pragma unroll
            for (int p = 0; p < 2; p++)
                ldsm4(bf[p], Bbase + (bbase[p] ^ cx));
#pragma unroll
            for (int mi = 0; mi < 3; mi++)
                ldsm4(af[mi], Abase + (abase[mi] ^ cx));
#pragma unroll
            for (int mi = 0; mi < 3; mi++)
#pragma unroll
                for (int ni = 0; ni < 4; ni++)
                    mma16816h(acc[mi][ni], af[mi], bf[ni >> 1][ni & 1], bf[ni >> 1][(ni & 1) + 2]);
        }
        __syncthreads();
    }
#undef PREFETCH

    const int gid = lane >> 2, tg = lane & 3;
#pragma unroll
    for (int mi = 0; mi < 3; mi++) {
#pragma unroll
        for (int ni = 0; ni < 4; ni++) {
            int n = n0 + wn * 32 + ni * 8 + tg * 2;
            bool nok = (n < HID);
#pragma unroll
            for (int half = 0; half < 2; half++) {
                int m = m0 + wm * 48 + mi * 16 + gid + half * 8;
                float v0 = acc[mi][ni][half * 2 + 0];
                float v1 = acc[mi][ni][half * 2 + 1];
                bool mok = (m < M);
                if (mok && nok) {
                    if (DO_BIAS) { v0 += bias[n]; v1 += bias[n + 1]; }
                    if (DO_SSP)  { v0 = ssp_f(v0); v1 = ssp_f(v1); }
                    if (DO_RSCALE) { float rs = rowscale[m]; v0 *= rs; v1 *= rs; }
                    if (OUTM == 0) {
                        *(float2*)(Cf + (size_t)m * HID + n) = make_float2(v0, v1);
                    } else if (OUTM == 2) {
                        float* cp = Cf + (size_t)m * HID + n;
                        float2 o = *(float2*)cp;
                        v0 += o.x; v1 += o.y;
                        *(float2*)cp = make_float2(v0, v1);
                    }
                    if (OUTM == 3) {
                        *(uint32_t*)(P + (size_t)m * pLd + n) = pack_h2(v0, v1);
                    }
                } else {
                    v0 = 0.0f; v1 = 0.0f;
                }
                if (OUTM == 1 || OUTM == 2) {
                    if (m < Mplane)
                        *(uint32_t*)(P + (size_t)m * pLd + n) = pack_h2(v0, v1);
                }
            }
        }
    }
}

// ---------------------------------------------------------------------------
// CSR aggregation: de-indirected payload, fp16 operands, fp32 accum.
// ---------------------------------------------------------------------------
__global__ __launch_bounds__(160)
void agg_kernel(const __half* __restrict__ xh, const __half* __restrict__ tab,
                __half* __restrict__ P) {
    int c = blockIdx.x;
    int lane = threadIdx.x;
    if (lane >= HID / 4) return;
    int s = g_off[c], epd = g_off[c + 1];
    float4 acc = make_float4(0.f, 0.f, 0.f, 0.f);
    const __half* xp = xh + 4 * lane;
    const __half* tp = tab + 4 * lane;
    int2 ri = make_int2(0, 0); float f = 0.f;
    if (s < epd) { ri = g_eri[s]; f = g_efc[s]; }
    for (int j = s; j < epd; j++) {
        uint2 xu  = *(const uint2*)(xp + (size_t)ri.x * KP);
        uint2 w0u = *(const uint2*)(tp + (size_t)ri.y * HID);
        uint2 w1u = *(const uint2*)(tp + (size_t)(ri.y + 1) * HID);
        int2 rin = ri; float fn = f;
        if (j + 1 < epd) { rin = g_eri[j + 1]; fn = g_efc[j + 1]; }
        float4 xv = h4_to_f4(xu);
        float4 w0 = h4_to_f4(w0u);
        float4 w1 = h4_to_f4(w1u);
        acc.x += xv.x * fmaf(f, w1.x - w0.x, w0.x);
        acc.y += xv.y * fmaf(f, w1.y - w0.y, w0.y);
        acc.z += xv.z * fmaf(f, w1.z - w0.z, w0.z);
        acc.w += xv.w * fmaf(f, w1.w - w0.w, w0.w);
        ri = rin; f = fn;
    }
    float av[4] = {acc.x, acc.y, acc.z, acc.w};
    *(uint2*)(P + (size_t)c * KP + 4 * lane) = pack_h4(av);
}

// ---------------------------------------------------------------------------
// Launch
// ---------------------------------------------------------------------------
extern "C" void kernel_launch(void* const* d_in, const int* in_sizes, int n_in,
                              void* d_out, int out_size) {
    const int*   z      = (const int*)  d_in[0];
    const float* pos    = (const float*)d_in[1];
    const int*   ei     = (const int*)  d_in[2];
    const float* emb    = (const float*)d_in[3];
    const float* mlp1_w = (const float*)d_in[4];
    const float* mlp1_b = (const float*)d_in[5];
    const float* mlp2_w = (const float*)d_in[6];
    const float* mlp2_b = (const float*)d_in[7];
    const float* lin1_w = (const float*)d_in[8];
    const float* lin2_w = (const float*)d_in[9];
    const float* lin2_b = (const float*)d_in[10];
    const float* lin_w  = (const float*)d_in[11];
    const float* lin_b  = (const float*)d_in[12];
    float* h = (float*)d_out;

    cudaFuncSetAttribute((const void*)hgemm<1,1,0,1>, cudaFuncAttributeMaxDynamicSharedMemorySize, SMEM_BYTES);
    cudaFuncSetAttribute((const void*)hgemm<1,0,1,3>, cudaFuncAttributeMaxDynamicSharedMemorySize, SMEM_BYTES);
    cudaFuncSetAttribute((const void*)hgemm<0,0,0,0>, cudaFuncAttributeMaxDynamicSharedMemorySize, SMEM_BYTES);
    cudaFuncSetAttribute((const void*)hgemm<0,0,0,1>, cudaFuncAttributeMaxDynamicSharedMemorySize, SMEM_BYTES);
    cudaFuncSetAttribute((const void*)hgemm<1,0,0,2>, cudaFuncAttributeMaxDynamicSharedMemorySize, SMEM_BYTES);

    __half *ea, *t1, *hh, *ag, *x2, *xh, *em, *w1, *wb, *tab;
    float *xe, *Ct;
    int *cnt;
    cudaGetSymbolAddress((void**)&ea, g_ea);   cudaGetSymbolAddress((void**)&t1, g_T1);
    cudaGetSymbolAddress((void**)&hh, g_h);    cudaGetSymbolAddress((void**)&ag, g_ag);
    cudaGetSymbolAddress((void**)&x2, g_x2);   cudaGetSymbolAddress((void**)&xh, g_xh);
    cudaGetSymbolAddress((void**)&em, g_em);   cudaGetSymbolAddress((void**)&w1, g_w1);
    cudaGetSymbolAddress((void**)&wb, g_wb);   cudaGetSymbolAddress((void**)&tab, g_tab);
    cudaGetSymbolAddress((void**)&xe, g_xe);   cudaGetSymbolAddress((void**)&Ct, g_Ct);
    cudaGetSymbolAddress((void**)&cnt, g_cnt);

    // Prologue
    cudaMemsetAsync(cnt, 0, NN * sizeof(int));
    {
        dim3 gW((600 * KP / 4 + 255) / 256, 1, NITR * 4);
        cvt_wb_kernel<<<gW, 256>>>(mlp2_w, lin1_w, lin2_w, lin_w);
        dim3 gW1((600 * KP1 + 255) / 256, 1, NITR);
        cvt_w1_kernel<<<gW1, 256>>>(mlp1_w);
    }
    prologue_kernel<<<B_TAB + B_EDGE + B_EMB + B_INIT, 256>>>(z, emb, pos, ei, h);
    // Table GEMMs (96-row tiles; plane writes guarded by Mplane=GT)
    {
        dim3 gT(5, MT96(GT), NITR);   // 5 x 11 x 6 = 330 blocks
        hgemm<1,1,0,1><<<gT, 256, SMEM_BYTES>>>(ea, w1,
            mlp1_b, nullptr, nullptr, t1, GT, GT, KP1, KP1, KP,
            0, (size_t)640 * KP1, HID, 0, (size_t)GT * KP);
        hgemm<1,0,1,3><<<gT, 256, SMEM_BYTES>>>(t1, wb,
            mlp2_b, Ct, nullptr, tab, GT, GT, KC, KP, HID,
            (size_t)GT * KP, (size_t)4 * 640 * KP, HID, 0, (size_t)GT * HID);
    }
    // Iteration-0 x via embedding table
    {
        __half* l1w0 = wb + (size_t)1 * 640 * KP;
        dim3 gZ(5, MT96(NZ), 1);   // 5 x 2
        hgemm<0,0,0,0><<<gZ, 256, SMEM_BYTES>>>(em, l1w0,
            nullptr, nullptr, xe, nullptr, NZ, NZ, KC, KP, 0, 0, 0, 0, 0, 0);
        xgather_kernel<<<(int)(((long)NN * HID / 4 + 255) / 256), 256>>>(z, xe, xh);
    }
    // CSR finalize
    csr_scan_kernel<<<1, 1024>>>();
    csr_place_kernel<<<(NE + 127) / 128, 128>>>(ei);

    dim3 gN(5, MT96(NN), 1);   // 5 x 105 = 525 tiles

    for (int it = 0; it < NITR; it++) {
        const float* l2b = lin2_b + (size_t)it * HID;
        const float* lb  = lin_b  + (size_t)it * HID;
        __half* l1w = wb + ((size_t)it * 4 + 1) * 640 * KP;
        __half* l2w = wb + ((size_t)it * 4 + 2) * 640 * KP;
        __half* lw  = wb + ((size_t)it * 4 + 3) * 640 * KP;

        if (it > 0) {
            hgemm<0,0,0,1><<<gN, 256, SMEM_BYTES>>>(hh, l1w,
                nullptr, nullptr, nullptr, xh, NN, NPAD, KC, KP, KP, 0, 0, 0, 0, 0);
        }
        agg_kernel<<<NN, 160>>>(xh, tab + (size_t)it * GT * HID, ag);
        hgemm<1,1,0,1><<<gN, 256, SMEM_BYTES>>>(ag, l2w,
            l2b, nullptr, nullptr, x2, NN, NPAD, KC, KP, KP, 0, 0, 0, 0, 0);
        hgemm<1,0,0,2><<<gN, 256, SMEM_BYTES>>>(x2, lw,
            lb, nullptr, h, hh, NN, NPAD, KC, KP, KP, 0, 0, 0, 0, 0);
    }
}

// round 17
// speedup vs baseline: 1.2144x; 1.0076x over previous
#include <cuda_runtime.h>
#include <cuda_bf16.h>
#include <cuda_fp16.h>
#include <math.h>
#include <stdint.h>

// Problem constants
#define NN   10000
#define NE   100000
#define HID  600
#define NGS  50
#define NITR 6
#define NZ   100

#define KP   640        // plane row stride (elements)
#define KC   608        // K compute extent
#define KP1  64
#define NPAD 10112
#define GT   1024
#define DMAX 13.86f
#define SMEM_BYTES (4 * 16384)   // max stage (128-row) x 4
#define MT96(M)  (((M) + 95) / 96)
#define MT128(M) (((M) + 127) / 128)

// ---------------------------------------------------------------------------
// Scratch
// ---------------------------------------------------------------------------
__device__ __align__(256) __half g_ea [(size_t)(GT + 32) * KP1];
__device__ __align__(256) __half g_T1 [(size_t)NITR * GT * KP + 96 * KP];
__device__ __align__(256) __half g_h  [(size_t)NPAD * KP];
__device__ __align__(256) __half g_ag [(size_t)NPAD * KP];
__device__ __align__(256) __half g_x2 [(size_t)NPAD * KP];
__device__ __align__(256) __half g_xh [(size_t)NPAD * KP];
__device__ __align__(256) __half g_em [(size_t)192 * KP];
__device__ __align__(256) __half g_w1 [(size_t)NITR * 640 * KP1];
__device__ __align__(256) __half g_wb [(size_t)NITR * 4 * 640 * KP];
__device__ __align__(256) __half g_tab[(size_t)NITR * GT * HID];
__device__ float g_xe  [(size_t)NZ * HID];
__device__ float g_Ct  [GT];
__device__ int   g_ei0 [NE];
__device__ float g_efr [NE];
__device__ int   g_cnt [NN];
__device__ int   g_off [NN + 1];
__device__ int   g_rank[NE];
__device__ int2  g_eri [NE];
__device__ float g_efc [NE];

// ---------------------------------------------------------------------------
// Helpers
// ---------------------------------------------------------------------------
__device__ __forceinline__ uint32_t smem_u32(const void* p) {
    uint32_t a;
    asm("{ .reg .u64 t; cvta.to.shared.u64 t, %1; cvt.u32.u64 %0, t; }" : "=r"(a) : "l"(p));
    return a;
}
__device__ __forceinline__ void ldsm4(uint32_t (&r)[4], uint32_t addr) {
    asm volatile("ldmatrix.sync.aligned.m8n8.x4.shared.b16 {%0,%1,%2,%3}, [%4];"
                 : "=r"(r[0]), "=r"(r[1]), "=r"(r[2]), "=r"(r[3]) : "r"(addr));
}
__device__ __forceinline__ void mma16816h(float (&d)[4], const uint32_t (&a)[4],
                                          uint32_t b0, uint32_t b1) {
    asm volatile("mma.sync.aligned.m16n8k16.row.col.f32.f16.f16.f32 "
                 "{%0,%1,%2,%3}, {%4,%5,%6,%7}, {%8,%9}, {%0,%1,%2,%3};"
                 : "+f"(d[0]), "+f"(d[1]), "+f"(d[2]), "+f"(d[3])
                 : "r"(a[0]), "r"(a[1]), "r"(a[2]), "r"(a[3]), "r"(b0), "r"(b1));
}
__device__ __forceinline__ void cpa16(uint32_t dst, const void* src) {
    asm volatile("cp.async.cg.shared.global [%0], [%1], 16;" :: "r"(dst), "l"(src));
}
__device__ __forceinline__ float ssp_f(float v) {
    float av = fabsf(v);
    return fmaxf(v, 0.0f) + log1pf(expf(-av)) - 0.69314718055994530942f;
}
__device__ __forceinline__ uint32_t pack_h2(float a, float b) {
    __half2 p = __floats2half2_rn(a, b);
    return *(uint32_t*)&p;
}
__device__ __forceinline__ uint2 pack_h4(const float* v) {
    uint2 u;
    u.x = pack_h2(v[0], v[1]);
    u.y = pack_h2(v[2], v[3]);
    return u;
}
__device__ __forceinline__ uint4 pack_h8(const float* v) {
    uint4 u;
    u.x = pack_h2(v[0], v[1]);
    u.y = pack_h2(v[2], v[3]);
    u.z = pack_h2(v[4], v[5]);
    u.w = pack_h2(v[6], v[7]);
    return u;
}
__device__ __forceinline__ float4 h4_to_f4(uint2 u) {
    float2 a = __half22float2(*(__half2*)&u.x);
    float2 b = __half22float2(*(__half2*)&u.y);
    return make_float4(a.x, a.y, b.x, b.y);
}

// ---------------------------------------------------------------------------
// Fused prologue (8-wide in the bulk sections)
// ---------------------------------------------------------------------------
#define B_TAB  (GT / 256)                 // 4
#define B_EDGE ((NE + 255) / 256)         // 391
#define B_EMB  ((128 * KP) / 2048)        // 40
#define B_INIT ((NN * KP) / 2048)         // 3125

__global__ void prologue_kernel(const int* __restrict__ z, const float* __restrict__ emb,
                                const float* __restrict__ pos, const int* __restrict__ ei,
                                float* __restrict__ hout) {
    int bx = blockIdx.x;
    if (bx < B_TAB) {
        int g = bx * 256 + threadIdx.x;
        float d = (float)g * (DMAX / (float)(GT - 1));
        g_Ct[g] = 0.5f * (cosf(d * (float)(M_PI / 10.0)) + 1.0f);
        const float step  = 10.0f / 49.0f;
        const float coeff = -0.5f / (step * step);
        __half* eh = g_ea + (size_t)g * KP1;
#pragma unroll 8
        for (int k = 0; k < KP1; k++) {
            float v = 0.0f;
            if (k < NGS) { float t = d - step * (float)k; v = expf(coeff * t * t); }
            eh[k] = __float2half_rn(v);
        }
    } else if (bx < B_TAB + B_EDGE) {
        int e = (bx - B_TAB) * 256 + threadIdx.x;
        if (e >= NE) return;
        int r = ei[e], c = ei[NE + e];
        float dx = pos[3*r+0] - pos[3*c+0];
        float dy = pos[3*r+1] - pos[3*c+1];
        float dz = pos[3*r+2] - pos[3*c+2];
        float d = sqrtf(dx*dx + dy*dy + dz*dz);
        float t = d * ((float)(GT - 1) / DMAX);
        int i0 = (int)t;
        if (i0 > GT - 2) i0 = GT - 2;
        g_ei0[e] = i0;
        g_efr[e] = t - (float)i0;
        g_rank[e] = atomicAdd(&g_cnt[c], 1);
    } else if (bx < B_TAB + B_EDGE + B_EMB) {
        long i = ((long)(bx - B_TAB - B_EDGE) * 256 + threadIdx.x) * 8;
        int r = (int)(i / KP), k = (int)(i - (long)r * KP);
        float v[8] = {0,0,0,0,0,0,0,0};
        if (r < NZ && k < HID) {
            *(float4*)v       = *(const float4*)(emb + (size_t)r * HID + k);
            *(float4*)(v + 4) = *(const float4*)(emb + (size_t)r * HID + k + 4);
        }
        *(uint4*)(g_em + i) = pack_h8(v);
    } else {
        long i = ((long)(bx - B_TAB - B_EDGE - B_EMB) * 256 + threadIdx.x) * 8;
        int n = (int)(i / KP), k = (int)(i - (long)n * KP);
        float v[8] = {0,0,0,0,0,0,0,0};
        if (k < HID) {
            const float* src = emb + (size_t)z[n] * HID + k;
            *(float4*)v       = *(const float4*)src;
            *(float4*)(v + 4) = *(const float4*)(src + 4);
            float* dst = hout + (size_t)n * HID + k;
            *(float4*)dst       = *(float4*)v;
            *(float4*)(dst + 4) = *(float4*)(v + 4);
        }
        *(uint4*)(g_h + i) = pack_h8(v);
    }
}

// Exclusive scan of g_cnt -> g_off
__global__ __launch_bounds__(1024)
void csr_scan_kernel() {
    __shared__ int part[1024];
    int t = threadIdx.x;
    int base = t * 10;
    int loc[10];
    int s = 0;
#pragma unroll
    for (int i = 0; i < 10; i++) {
        int idx = base + i;
        loc[i] = s;
        s += (idx < NN) ? g_cnt[idx] : 0;
    }
    part[t] = s;
    __syncthreads();
    for (int off = 1; off < 1024; off <<= 1) {
        int v = (t >= off) ? part[t - off] : 0;
        __syncthreads();
        if (t >= off) part[t] += v;
        __syncthreads();
    }
    int pre = (t > 0) ? part[t - 1] : 0;
#pragma unroll
    for (int i = 0; i < 10; i++) {
        int idx = base + i;
        if (idx < NN) g_off[idx] = pre + loc[i];
    }
    if (t == 1023) g_off[NN] = part[1023];
}

__global__ void csr_place_kernel(const int* __restrict__ ei) {
    int e = blockIdx.x * blockDim.x + threadIdx.x;
    if (e >= NE) return;
    int c = ei[NE + e];
    int j = g_off[c] + g_rank[e];
    g_eri[j] = make_int2(ei[e], g_ei0[e]);
    g_efc[j] = g_efr[e];
}

// Batched 8-wide convert of 24 HID x HID weights
__global__ void cvt_wb_kernel(const float* __restrict__ w2, const float* __restrict__ l1,
                              const float* __restrict__ l2, const float* __restrict__ lw) {
    int zz = blockIdx.z;
    int wix = zz & 3, it = zz >> 2;
    const float* src = ((wix == 0) ? w2 : (wix == 1) ? l1 : (wix == 2) ? l2 : lw)
                       + (size_t)it * HID * HID;
    __half* dh = g_wb + (size_t)zz * 640 * KP;
    long i = ((long)blockIdx.x * blockDim.x + threadIdx.x) * 8;
    if (i >= (long)600 * KP) return;
    int r = (int)(i / KP), k = (int)(i - (long)r * KP);
    float v[8] = {0,0,0,0,0,0,0,0};
    if (k < HID) {
        *(float4*)v       = *(const float4*)(src + (size_t)r * HID + k);
        *(float4*)(v + 4) = *(const float4*)(src + (size_t)r * HID + k + 4);
    }
    *(uint4*)(dh + i) = pack_h8(v);
}

__global__ void cvt_w1_kernel(const float* __restrict__ w1) {
    int it = blockIdx.z;
    const float* src = w1 + (size_t)it * HID * NGS;
    __half* dh = g_w1 + (size_t)it * 640 * KP1;
    long i = blockIdx.x * (long)blockDim.x + threadIdx.x;
    if (i >= (long)600 * KP1) return;
    int r = (int)(i / KP1), k = (int)(i - (long)r * KP1);
    float v = (k < NGS) ? src[(size_t)r * NGS + k] : 0.0f;
    dh[i] = __float2half_rn(v);
}

// x plane[n] = fp16(xe[z[n]])
__global__ void xgather_kernel(const int* __restrict__ z, const float* __restrict__ xe,
                               __half* __restrict__ xh) {
    long i = ((long)blockIdx.x * blockDim.x + threadIdx.x) * 4;
    if (i >= (long)NN * HID) return;
    int n = (int)(i / HID), k = (int)(i - (long)n * HID);
    float v[4];
    *(float4*)v = *(const float4*)(xe + (size_t)z[n] * HID + k);
    *(uint2*)(xh + (size_t)n * KP + k) = pack_h4(v);
}

// ---------------------------------------------------------------------------
// fp16 HMMA GEMM, (MFRAG*32)x128 tile, 2 CTAs/SM, 4-stage pipeline.
// MFRAG=4 -> 128-row tile; MFRAG=3 -> 96-row tile.
// OUTM: 0 fp32 Cf; 1 fp16 plane (zero-pads, guarded by Mplane);
//       2 fp32 residual + plane; 3 fp16 valid-only
// ---------------------------------------------------------------------------
template <int MFRAG, int DO_BIAS, int DO_SSP, int DO_RSCALE, int OUTM>
__global__ __launch_bounds__(256, 2)
void hgemm(const __half* __restrict__ A, const __half* __restrict__ B,
           const float* __restrict__ bias, const float* __restrict__ rowscale,
           float* __restrict__ Cf, __half* __restrict__ P,
           int M, int Mplane, int Kc, int ldA, int pLd,
           size_t aZ, size_t bZ, size_t biasZ, size_t cZ, size_t pZ) {
    constexpr int MTILE = MFRAG * 32;          // 96 or 128
    constexpr int ABYTES = MTILE * 64;         // A stage bytes
    constexpr int STGB = ABYTES + 8192;        // stage bytes
    extern __shared__ char smem[];
    const uint32_t sb = smem_u32(smem);
    const int tid = threadIdx.x, lane = tid & 31, wid = tid >> 5;
    const int wm = wid >> 2, wn = wid & 3;
    const int m0 = blockIdx.y * MTILE, n0 = blockIdx.x * 128;
    const int zz = blockIdx.z;

    A += (size_t)zz * aZ;
    B += (size_t)zz * bZ;
    if (DO_BIAS)   bias += (size_t)zz * biasZ;
    if (OUTM == 0 || OUTM == 2) Cf += (size_t)zz * cZ;
    if (OUTM >= 1) P += (size_t)zz * pZ;

    float acc[MFRAG][4][4];
#pragma unroll
    for (int a = 0; a < MFRAG; a++)
#pragma unroll
        for (int b = 0; b < 4; b++)
#pragma unroll
            for (int c = 0; c < 4; c++) acc[a][b][c] = 0.0f;

    const int lr = tid >> 2;
    const int lc = tid & 3;

    const int arow = wm * (MFRAG * 16) + (lane & 15);
    const int brow = wn * 32 + (lane & 15);
    uint32_t abase[MFRAG], bbase[2];
#pragma unroll
    for (int mi = 0; mi < MFRAG; mi++) {
        int r = arow + mi * 16;
        abase[mi] = (uint32_t)(r * 64 + (((r >> 1) & 3) * 16));
    }
#pragma unroll
    for (int p = 0; p < 2; p++) {
        int r = brow + p * 16;
        bbase[p] = (uint32_t)(r * 64 + (((r >> 1) & 3) * 16));
    }

#define PREFETCH(chunk, stg) do {                                              \
        uint32_t sbase = sb + (stg) * STGB;                                    \
        int k0 = (chunk) * 32;                                                 \
        _Pragma("unroll")                                                      \
        for (int i = 0; i < 2; i++) {                                          \
            int r = i * 64 + lr;                                               \
            uint32_t sw = (uint32_t)((lc ^ ((r >> 1) & 3)) * 16);              \
            if (MTILE == 128 || r < MTILE)                                     \
                cpa16(sbase + r * 64 + sw,                                     \
                      A + (size_t)(m0 + r) * ldA + k0 + lc * 8);               \
            cpa16(sbase + ABYTES + r * 64 + sw,                                \
                  B + (size_t)(n0 + r) * ldA + k0 + lc * 8);                   \
        }                                                                      \
        asm volatile("cp.async.commit_group;" ::: "memory");                   \
    } while (0)

    const int nc = Kc >> 5;
    PREFETCH(0, 0);
    if (nc > 1) PREFETCH(1, 1);
    if (nc > 2) PREFETCH(2, 2);
    for (int ch = 0; ch < nc; ch++) {
        int stg = ch & 3;
        if (ch + 2 < nc) {
            asm volatile("cp.async.wait_group 2;" ::: "memory");
        } else if (ch + 1 < nc) {
            asm volatile("cp.async.wait_group 1;" ::: "memory");
        } else {
            asm volatile("cp.async.wait_group 0;" ::: "memory");
        }
        __syncthreads();
        if (ch + 3 < nc) PREFETCH(ch + 3, (ch + 3) & 3);

        uint32_t Abase = sb + stg * STGB;
        uint32_t Bbase = Abase + ABYTES;
#pragma unroll
        for (int ks = 0; ks < 2; ks++) {
            uint32_t cx = (uint32_t)((ks * 2 + (lane >> 4)) * 16);
            uint32_t af[MFRAG][4], bf[2][4];
#pragma unroll
            for (int p = 0; p < 2; p++)
                ldsm4(bf[p], Bbase + (bbase[p] ^ cx));
#pragma unroll
            for (int mi = 0; mi < MFRAG; mi++)
                ldsm4(af[mi], Abase + (abase[mi] ^ cx));
#pragma unroll
            for (int mi = 0; mi < MFRAG; mi++)
#pragma unroll
                for (int ni = 0; ni < 4; ni++)
                    mma16816h(acc[mi][ni], af[mi], bf[ni >> 1][ni & 1], bf[ni >> 1][(ni & 1) + 2]);
        }
        __syncthreads();
    }
#undef PREFETCH

    const int gid = lane >> 2, tg = lane & 3;
#pragma unroll
    for (int mi = 0; mi < MFRAG; mi++) {
#pragma unroll
        for (int ni = 0; ni < 4; ni++) {
            int n = n0 + wn * 32 + ni * 8 + tg * 2;
            bool nok = (n < HID);
#pragma unroll
            for (int half = 0; half < 2; half++) {
                int m = m0 + wm * (MFRAG * 16) + mi * 16 + gid + half * 8;
                float v0 = acc[mi][ni][half * 2 + 0];
                float v1 = acc[mi][ni][half * 2 + 1];
                bool mok = (m < M);
                if (mok && nok) {
                    if (DO_BIAS) { v0 += bias[n]; v1 += bias[n + 1]; }
                    if (DO_SSP)  { v0 = ssp_f(v0); v1 = ssp_f(v1); }
                    if (DO_RSCALE) { float rs = rowscale[m]; v0 *= rs; v1 *= rs; }
                    if (OUTM == 0) {
                        *(float2*)(Cf + (size_t)m * HID + n) = make_float2(v0, v1);
                    } else if (OUTM == 2) {
                        float* cp = Cf + (size_t)m * HID + n;
                        float2 o = *(float2*)cp;
                        v0 += o.x; v1 += o.y;
                        *(float2*)cp = make_float2(v0, v1);
                    }
                    if (OUTM == 3) {
                        *(uint32_t*)(P + (size_t)m * pLd + n) = pack_h2(v0, v1);
                    }
                } else {
                    v0 = 0.0f; v1 = 0.0f;
                }
                if (OUTM == 1 || OUTM == 2) {
                    if (m < Mplane)
                        *(uint32_t*)(P + (size_t)m * pLd + n) = pack_h2(v0, v1);
                }
            }
        }
    }
}

// ---------------------------------------------------------------------------
// CSR aggregation: de-indirected payload, fp16 operands, fp32 accum.
// ---------------------------------------------------------------------------
__global__ __launch_bounds__(160)
void agg_kernel(const __half* __restrict__ xh, const __half* __restrict__ tab,
                __half* __restrict__ P) {
    int c = blockIdx.x;
    int lane = threadIdx.x;
    if (lane >= HID / 4) return;
    int s = g_off[c], epd = g_off[c + 1];
    float4 acc = make_float4(0.f, 0.f, 0.f, 0.f);
    const __half* xp = xh + 4 * lane;
    const __half* tp = tab + 4 * lane;
    int2 ri = make_int2(0, 0); float f = 0.f;
    if (s < epd) { ri = g_eri[s]; f = g_efc[s]; }
    for (int j = s; j < epd; j++) {
        uint2 xu  = *(const uint2*)(xp + (size_t)ri.x * KP);
        uint2 w0u = *(const uint2*)(tp + (size_t)ri.y * HID);
        uint2 w1u = *(const uint2*)(tp + (size_t)(ri.y + 1) * HID);
        int2 rin = ri; float fn = f;
        if (j + 1 < epd) { rin = g_eri[j + 1]; fn = g_efc[j + 1]; }
        float4 xv = h4_to_f4(xu);
        float4 w0 = h4_to_f4(w0u);
        float4 w1 = h4_to_f4(w1u);
        acc.x += xv.x * fmaf(f, w1.x - w0.x, w0.x);
        acc.y += xv.y * fmaf(f, w1.y - w0.y, w0.y);
        acc.z += xv.z * fmaf(f, w1.z - w0.z, w0.z);
        acc.w += xv.w * fmaf(f, w1.w - w0.w, w0.w);
        ri = rin; f = fn;
    }
    float av[4] = {acc.x, acc.y, acc.z, acc.w};
    *(uint2*)(P + (size_t)c * KP + 4 * lane) = pack_h4(av);
}

// ---------------------------------------------------------------------------
// Launch
// ---------------------------------------------------------------------------
extern "C" void kernel_launch(void* const* d_in, const int* in_sizes, int n_in,
                              void* d_out, int out_size) {
    const int*   z      = (const int*)  d_in[0];
    const float* pos    = (const float*)d_in[1];
    const int*   ei     = (const int*)  d_in[2];
    const float* emb    = (const float*)d_in[3];
    const float* mlp1_w = (const float*)d_in[4];
    const float* mlp1_b = (const float*)d_in[5];
    const float* mlp2_w = (const float*)d_in[6];
    const float* mlp2_b = (const float*)d_in[7];
    const float* lin1_w = (const float*)d_in[8];
    const float* lin2_w = (const float*)d_in[9];
    const float* lin2_b = (const float*)d_in[10];
    const float* lin_w  = (const float*)d_in[11];
    const float* lin_b  = (const float*)d_in[12];
    float* h = (float*)d_out;

    cudaFuncSetAttribute((const void*)hgemm<4,1,1,0,1>, cudaFuncAttributeMaxDynamicSharedMemorySize, SMEM_BYTES);
    cudaFuncSetAttribute((const void*)hgemm<4,1,0,1,3>, cudaFuncAttributeMaxDynamicSharedMemorySize, SMEM_BYTES);
    cudaFuncSetAttribute((const void*)hgemm<4,0,0,0,0>, cudaFuncAttributeMaxDynamicSharedMemorySize, SMEM_BYTES);
    cudaFuncSetAttribute((const void*)hgemm<3,0,0,0,1>, cudaFuncAttributeMaxDynamicSharedMemorySize, SMEM_BYTES);
    cudaFuncSetAttribute((const void*)hgemm<3,1,1,0,1>, cudaFuncAttributeMaxDynamicSharedMemorySize, SMEM_BYTES);
    cudaFuncSetAttribute((const void*)hgemm<3,1,0,0,2>, cudaFuncAttributeMaxDynamicSharedMemorySize, SMEM_BYTES);

    __half *ea, *t1, *hh, *ag, *x2, *xh, *em, *w1, *wb, *tab;
    float *xe, *Ct;
    int *cnt;
    cudaGetSymbolAddress((void**)&ea, g_ea);   cudaGetSymbolAddress((void**)&t1, g_T1);
    cudaGetSymbolAddress((void**)&hh, g_h);    cudaGetSymbolAddress((void**)&ag, g_ag);
    cudaGetSymbolAddress((void**)&x2, g_x2);   cudaGetSymbolAddress((void**)&xh, g_xh);
    cudaGetSymbolAddress((void**)&em, g_em);   cudaGetSymbolAddress((void**)&w1, g_w1);
    cudaGetSymbolAddress((void**)&wb, g_wb);   cudaGetSymbolAddress((void**)&tab, g_tab);
    cudaGetSymbolAddress((void**)&xe, g_xe);   cudaGetSymbolAddress((void**)&Ct, g_Ct);
    cudaGetSymbolAddress((void**)&cnt, g_cnt);

    // Prologue
    cudaMemsetAsync(cnt, 0, NN * sizeof(int));
    {
        dim3 gW((600 * KP / 8 + 255) / 256, 1, NITR * 4);
        cvt_wb_kernel<<<gW, 256>>>(mlp2_w, lin1_w, lin2_w, lin_w);
        dim3 gW1((600 * KP1 + 255) / 256, 1, NITR);
        cvt_w1_kernel<<<gW1, 256>>>(mlp1_w);
    }
    prologue_kernel<<<B_TAB + B_EDGE + B_EMB + B_INIT, 256>>>(z, emb, pos, ei, h);
    // Table GEMMs (128-row tiles: 240 blocks = 1 wave at 2 CTAs/SM)
    {
        dim3 gT(5, MT128(GT), NITR);   // 5 x 8 x 6 = 240
        hgemm<4,1,1,0,1><<<gT, 256, SMEM_BYTES>>>(ea, w1,
            mlp1_b, nullptr, nullptr, t1, GT, GT, KP1, KP1, KP,
            0, (size_t)640 * KP1, HID, 0, (size_t)GT * KP);
        hgemm<4,1,0,1,3><<<gT, 256, SMEM_BYTES>>>(t1, wb,
            mlp2_b, Ct, nullptr, tab, GT, GT, KC, KP, HID,
            (size_t)GT * KP, (size_t)4 * 640 * KP, HID, 0, (size_t)GT * HID);
    }
    // Iteration-0 x via embedding table
    {
        __half* l1w0 = wb + (size_t)1 * 640 * KP;
        dim3 gZ(5, MT128(NZ), 1);   // 5 x 1
        hgemm<4,0,0,0,0><<<gZ, 256, SMEM_BYTES>>>(em, l1w0,
            nullptr, nullptr, xe, nullptr, NZ, NZ, KC, KP, 0, 0, 0, 0, 0, 0);
        xgather_kernel<<<(int)(((long)NN * HID / 4 + 255) / 256), 256>>>(z, xe, xh);
    }
    // CSR finalize
    csr_scan_kernel<<<1, 1024>>>();
    csr_place_kernel<<<(NE + 127) / 128, 128>>>(ei);

    dim3 gN(5, MT96(NN), 1);   // 5 x 105 node tiles (96-row)

    for (int it = 0; it < NITR; it++) {
        const float* l2b = lin2_b + (size_t)it * HID;
        const float* lb  = lin_b  + (size_t)it * HID;
        __half* l1w = wb + ((size_t)it * 4 + 1) * 640 * KP;
        __half* l2w = wb + ((size_t)it * 4 + 2) * 640 * KP;
        __half* lw  = wb + ((size_t)it * 4 + 3) * 640 * KP;

        if (it > 0) {
            hgemm<3,0,0,0,1><<<gN, 256, SMEM_BYTES>>>(hh, l1w,
                nullptr, nullptr, nullptr, xh, NN, NPAD, KC, KP, KP, 0, 0, 0, 0, 0);
        }
        agg_kernel<<<NN, 160>>>(xh, tab + (size_t)it * GT * HID, ag);
        hgemm<3,1,1,0,1><<<gN, 256, SMEM_BYTES>>>(ag, l2w,
            l2b, nullptr, nullptr, x2, NN, NPAD, KC, KP, KP, 0, 0, 0, 0, 0);
        // Last iteration: skip dead plane stores (Mplane = 0)
        int mp = (it == NITR - 1) ? 0 : NPAD;
        hgemm<3,1,0,0,2><<<gN, 256, SMEM_BYTES>>>(x2, lw,
            lb, nullptr, h, hh, NN, mp, KC, KP, KP, 0, 0, 0, 0, 0);
    }
}